// round 3
// baseline (speedup 1.0000x reference)
#include <cuda_runtime.h>
#include <cuda_bf16.h>
#include <math.h>

// ---------------- compile-time architecture dims ----------------
#define F_DIM 128
#define H_DIM 64
#define C_DIM 10
#define P_DIM 384           // 2*(F+H)
#define N_CAP 100000
#define R_CAP 16
#define G_CAP 1024

// ---------------- scratch (static device arrays; no allocs) -----
__device__ float d_W[R_CAP * H_DIM * H_DIM];   // 256 KB
__device__ float d_y[(size_t)N_CAP * H_DIM];   // 25.6 MB  x @ w1_rel
__device__ float d_h[(size_t)N_CAP * H_DIM];   // 25.6 MB  node hidden
__device__ float d_o[(size_t)N_CAP * H_DIM];   // 25.6 MB  rgcn out
__device__ int   d_cnt[(size_t)N_CAP * R_CAP]; // 6.4 MB   per (node, rel) counts
__device__ float d_pool[(size_t)G_CAP * P_DIM];
__device__ int   d_offs[G_CAP + 1];

// ---------------- vector reductions (sm_90+) --------------------
__device__ __forceinline__ void red_add_v4(float* addr, float a, float b, float c, float d) {
    asm volatile("red.global.add.v4.f32 [%0], {%1, %2, %3, %4};"
                 :: "l"(addr), "f"(a), "f"(b), "f"(c), "f"(d) : "memory");
}
__device__ __forceinline__ void red_add_v2(float* addr, float a, float b) {
    asm volatile("red.global.add.v2.f32 [%0], {%1, %2};"
                 :: "l"(addr), "f"(a), "f"(b) : "memory");
}

// ---------------- k_prep: zero counts, W = comp @ bases ----------
__global__ void k_prep(const float* __restrict__ comp, const float* __restrict__ bases,
                       int R, int NB, int N) {
    int tid = blockIdx.x * blockDim.x + threadIdx.x;
    int nth = gridDim.x * blockDim.x;
    int total_cnt = N * R;
    for (int i = tid; i < total_cnt; i += nth) d_cnt[i] = 0;
    int wtot = R * H_DIM * H_DIM;
    for (int i = tid; i < wtot; i += nth) {
        int r = i >> 12;          // / 4096
        int ij = i & 4095;
        float acc = 0.f;
        for (int b = 0; b < NB; b++)
            acc += comp[r * NB + b] * bases[b * 4096 + ij];
        d_W[i] = acc;
    }
}

// ---------------- k_scan: exclusive prefix of seq_lengths -------
__global__ void k_scan(const int* __restrict__ sl, int G) {
    __shared__ int s[1024];
    int t = threadIdx.x;
    s[t] = (t < G) ? sl[t] : 0;
    __syncthreads();
    for (int off = 1; off < 1024; off <<= 1) {
        int add = (t >= off) ? s[t - off] : 0;
        __syncthreads();
        s[t] += add;
        __syncthreads();
    }
    if (t == 0) d_offs[0] = 0;
    if (t < G) d_offs[t + 1] = s[t];
}

// ---------------- k_proj: y = x@w1_rel ; h = x@w1_root + b1 -----
// warp processes 2 nodes; weights (64KB) + per-warp x stage in dyn smem
__global__ void k_proj(const float* __restrict__ x, const float* __restrict__ w_rel,
                       const float* __restrict__ w_root, const float* __restrict__ b1,
                       int N) {
    extern __shared__ float sw[];   // [0,8192) w_rel, [8192,16384) w_root, then 256/warp x-stage
    for (int i = threadIdx.x; i < 8192; i += blockDim.x) {
        sw[i] = w_rel[i];
        sw[8192 + i] = w_root[i];
    }
    __syncthreads();
    int lane = threadIdx.x & 31;
    int wl   = threadIdx.x >> 5;
    int warp = (blockIdx.x * blockDim.x + threadIdx.x) >> 5;
    int nw   = (gridDim.x * blockDim.x) >> 5;
    float* sx = sw + 16384 + wl * 256;
    float bias0 = b1[2 * lane], bias1 = b1[2 * lane + 1];
    int npairs = (N + 1) >> 1;
    for (int p = warp; p < npairs; p += nw) {
        int n0 = 2 * p, n1 = 2 * p + 1;
        bool has1 = n1 < N;
        float4 xa = *(const float4*)(x + (size_t)n0 * F_DIM + 4 * lane);
        float4 xb = has1 ? *(const float4*)(x + (size_t)n1 * F_DIM + 4 * lane)
                         : make_float4(0.f, 0.f, 0.f, 0.f);
        *(float4*)(sx + 4 * lane) = xa;
        *(float4*)(sx + 128 + 4 * lane) = xb;
        __syncwarp();
        float ya0 = 0, ya1 = 0, ha0 = 0, ha1 = 0;
        float yb0 = 0, yb1 = 0, hb0 = 0, hb1 = 0;
#pragma unroll 8
        for (int k = 0; k < F_DIM; k++) {
            float x0 = sx[k];
            float x1 = sx[128 + k];
            float2 wr = *(const float2*)(sw + k * 64 + 2 * lane);
            float2 wo = *(const float2*)(sw + 8192 + k * 64 + 2 * lane);
            ya0 += x0 * wr.x; ya1 += x0 * wr.y;
            ha0 += x0 * wo.x; ha1 += x0 * wo.y;
            yb0 += x1 * wr.x; yb1 += x1 * wr.y;
            hb0 += x1 * wo.x; hb1 += x1 * wo.y;
        }
        *(float2*)(d_y + (size_t)n0 * H_DIM + 2 * lane) = make_float2(ya0, ya1);
        *(float2*)(d_h + (size_t)n0 * H_DIM + 2 * lane) = make_float2(ha0 + bias0, ha1 + bias1);
        if (has1) {
            *(float2*)(d_y + (size_t)n1 * H_DIM + 2 * lane) = make_float2(yb0, yb1);
            *(float2*)(d_h + (size_t)n1 * H_DIM + 2 * lane) = make_float2(hb0 + bias0, hb1 + bias1);
        }
        __syncwarp();
    }
}

// ---------------- k_count: per (dst, rel) edge counts -----------
__global__ void k_count(const int* __restrict__ ei, const int* __restrict__ et,
                        int E, int R) {
    int e = blockIdx.x * blockDim.x + threadIdx.x;
    if (e >= E) return;
    int dst = ei[E + e];
    atomicAdd(&d_cnt[(size_t)dst * R + et[e]], 1);
}

// ---------------- k_agg1: h[dst] += y[src]*norm (16 thr/edge) ---
__global__ void k_agg1(const int* __restrict__ ei, const float* __restrict__ nrm, int E) {
    int t = blockIdx.x * blockDim.x + threadIdx.x;
    int e = t >> 4;
    if (e >= E) return;
    int sub = t & 15;
    int src = ei[e];
    int dst = ei[E + e];
    float w = nrm[e];
    float4 v = *(const float4*)(d_y + (size_t)src * H_DIM + sub * 4);
    red_add_v4(d_h + (size_t)dst * H_DIM + sub * 4, v.x * w, v.y * w, v.z * w, v.w * w);
}

// ---------------- k_oroot: o = h @ w2_root + b2 -----------------
__global__ void k_oroot(const float* __restrict__ w2, const float* __restrict__ b2, int N) {
    __shared__ float sw[4096];
    __shared__ float sx[8][128];   // 2 nodes * 64 per warp
    for (int i = threadIdx.x; i < 4096; i += blockDim.x) sw[i] = w2[i];
    __syncthreads();
    int lane = threadIdx.x & 31;
    int wl   = threadIdx.x >> 5;
    int warp = (blockIdx.x * blockDim.x + threadIdx.x) >> 5;
    int nw   = (gridDim.x * blockDim.x) >> 5;
    float bias0 = b2[2 * lane], bias1 = b2[2 * lane + 1];
    int npairs = (N + 1) >> 1;
    for (int p = warp; p < npairs; p += nw) {
        int n0 = 2 * p, n1 = 2 * p + 1;
        bool has1 = n1 < N;
        float2 h0 = *(const float2*)(d_h + (size_t)n0 * H_DIM + 2 * lane);
        float2 h1 = has1 ? *(const float2*)(d_h + (size_t)n1 * H_DIM + 2 * lane)
                         : make_float2(0.f, 0.f);
        *(float2*)(&sx[wl][2 * lane]) = h0;
        *(float2*)(&sx[wl][64 + 2 * lane]) = h1;
        __syncwarp();
        float a0 = 0, a1 = 0, c0 = 0, c1 = 0;
#pragma unroll 8
        for (int k = 0; k < H_DIM; k++) {
            float x0 = sx[wl][k];
            float x1 = sx[wl][64 + k];
            float2 w = *(const float2*)(sw + k * 64 + 2 * lane);
            a0 += x0 * w.x; a1 += x0 * w.y;
            c0 += x1 * w.x; c1 += x1 * w.y;
        }
        *(float2*)(d_o + (size_t)n0 * H_DIM + 2 * lane) = make_float2(a0 + bias0, a1 + bias1);
        if (has1)
            *(float2*)(d_o + (size_t)n1 * H_DIM + 2 * lane) = make_float2(c0 + bias0, c1 + bias1);
        __syncwarp();
    }
}

// ---------------- k_rgcn: o[dst] += (h[src] @ W[type]) / c ------
__global__ void k_rgcn(const int* __restrict__ ei, const int* __restrict__ et,
                       int E, int R) {
    __shared__ float sh[8][64];
    int lane = threadIdx.x & 31;
    int wl   = threadIdx.x >> 5;
    int gw   = (blockIdx.x * blockDim.x + threadIdx.x) >> 5;
    int nw   = (gridDim.x * blockDim.x) >> 5;
    for (int e = gw; e < E; e += nw) {
        int src = ei[e];
        int dst = ei[E + e];
        int r   = et[e];
        const float* __restrict__ W = d_W + (size_t)r * 4096;
        float2 hv = *(const float2*)(d_h + (size_t)src * H_DIM + 2 * lane);
        *(float2*)(&sh[wl][2 * lane]) = hv;
        __syncwarp();
        float a0 = 0.f, a1 = 0.f;
#pragma unroll
        for (int k = 0; k < H_DIM; k++) {
            float xk = sh[wl][k];
            float2 w = *(const float2*)(W + k * 64 + 2 * lane);
            a0 += xk * w.x;
            a1 += xk * w.y;
        }
        int c = d_cnt[(size_t)dst * R + r];
        float inv = 1.f / (float)(c > 1 ? c : 1);
        red_add_v2(d_o + (size_t)dst * H_DIM + 2 * lane, a0 * inv, a1 * inv);
        __syncwarp();
    }
}

// ---------------- k_pool: per-graph sum + max -------------------
__global__ void k_pool(const float* __restrict__ x, int G) {
    int g = blockIdx.x;
    int s = d_offs[g], e = d_offs[g + 1];
    int d = threadIdx.x;                 // 192 threads
    float sum = 0.f, mx = -INFINITY;
    if (d < F_DIM) {
        for (int n = s; n < e; n++) {
            float v = x[(size_t)n * F_DIM + d];
            sum += v; mx = fmaxf(mx, v);
        }
    } else {
        int dd = d - F_DIM;
        for (int n = s; n < e; n++) {
            float v = d_o[(size_t)n * H_DIM + dd];
            sum += v; mx = fmaxf(mx, v);
        }
    }
    d_pool[(size_t)g * P_DIM + d] = sum;
    d_pool[(size_t)g * P_DIM + 192 + d] = mx;
}

// ---------------- k_head: linear->relu->linear->log_softmax -----
__global__ void k_head(const float* __restrict__ lin_w, const float* __restrict__ lin_b,
                       const float* __restrict__ fc_w, const float* __restrict__ fc_b,
                       float* __restrict__ out, int G) {
    __shared__ float sp[P_DIM];
    __shared__ float hid[H_DIM];
    __shared__ float lg[C_DIM];
    __shared__ float lse;
    int g = blockIdx.x, t = threadIdx.x;   // 64 threads
    for (int i = t; i < P_DIM; i += 64) sp[i] = d_pool[(size_t)g * P_DIM + i];
    __syncthreads();
    float acc = lin_b[t];
#pragma unroll 8
    for (int k = 0; k < P_DIM; k++) acc += sp[k] * lin_w[k * H_DIM + t];
    hid[t] = fmaxf(acc, 0.f);
    __syncthreads();
    if (t < C_DIM) {
        float a = fc_b[t];
#pragma unroll
        for (int k = 0; k < H_DIM; k++) a += hid[k] * fc_w[k * C_DIM + t];
        lg[t] = a;
    }
    __syncthreads();
    if (t == 0) {
        float m = -INFINITY;
        for (int j = 0; j < C_DIM; j++) m = fmaxf(m, lg[j]);
        float s2 = 0.f;
        for (int j = 0; j < C_DIM; j++) s2 += expf(lg[j] - m);
        lse = m + logf(s2);
    }
    __syncthreads();
    if (t < C_DIM) out[(size_t)g * C_DIM + t] = lg[t] - lse;
}

// ---------------- launch ----------------------------------------
extern "C" void kernel_launch(void* const* d_in, const int* in_sizes, int n_in,
                              void* d_out, int out_size) {
    // avec may or may not be materialized as an input; detect by count.
    int o = (n_in >= 17) ? 0 : -1;
    const float* x       = (const float*)d_in[0];
    const int*   ei      = (const int*)d_in[1];
    const float* enorm   = (const float*)d_in[2];
    const int*   etype   = (const int*)d_in[3];
    const int*   seql    = (const int*)d_in[4];
    const float* w1_rel  = (const float*)d_in[6 + o];
    const float* w1_root = (const float*)d_in[7 + o];
    const float* b1      = (const float*)d_in[8 + o];
    const float* bases   = (const float*)d_in[9 + o];
    const float* comp    = (const float*)d_in[10 + o];
    const float* w2      = (const float*)d_in[11 + o];
    const float* b2      = (const float*)d_in[12 + o];
    const float* lin_w   = (const float*)d_in[13 + o];
    const float* lin_b   = (const float*)d_in[14 + o];
    const float* fc_w    = (const float*)d_in[15 + o];
    const float* fc_b    = (const float*)d_in[16 + o];

    int N  = in_sizes[0] / F_DIM;
    int E  = in_sizes[2];
    int G  = in_sizes[4];
    int NB = in_sizes[9 + o] / (H_DIM * H_DIM);
    int R  = in_sizes[10 + o] / NB;
    float* out = (float*)d_out;
    (void)out_size;

    cudaFuncSetAttribute(k_proj, cudaFuncAttributeMaxDynamicSharedMemorySize, 73728);

    k_prep<<<2048, 256>>>(comp, bases, R, NB, N);
    k_scan<<<1, 1024>>>(seql, G);
    k_proj<<<592, 256, 73728>>>(x, w1_rel, w1_root, b1, N);
    k_count<<<(E + 255) / 256, 256>>>(ei, etype, E, R);
    {
        long long t = (long long)E * 16;
        k_agg1<<<(int)((t + 255) / 256), 256>>>(ei, enorm, E);
    }
    k_oroot<<<592, 256>>>(w2, b2, N);
    k_rgcn<<<2048, 256>>>(ei, etype, E, R);
    k_pool<<<G, 192>>>(x, G);
    k_head<<<G, 64>>>(lin_w, lin_b, fc_w, fc_b, out, G);
}

// round 6
// speedup vs baseline: 1.5025x; 1.5025x over previous
#include <cuda_runtime.h>
#include <cuda_bf16.h>
#include <math.h>

// ---------------- compile-time architecture dims ----------------
#define F_DIM 128
#define H_DIM 64
#define C_DIM 10
#define P_DIM 384           // 2*(F+H)
#define N_CAP 100000
#define R_CAP 16
#define G_CAP 1024
#define E_CAP 1000000
#define NBLK_B 512          // blocks for hist/scatter passes

// ---------------- scratch (static device arrays; no allocs) -----
__device__ float d_W[R_CAP * H_DIM * H_DIM];   // 256 KB  [r][k][n]
__device__ float d_y[(size_t)N_CAP * H_DIM];   // 25.6 MB  x @ w1_rel
__device__ float d_h[(size_t)N_CAP * H_DIM];   // 25.6 MB  node hidden
__device__ float d_o[(size_t)N_CAP * H_DIM];   // 25.6 MB  rgcn out
__device__ int   d_cnt[(size_t)N_CAP * R_CAP]; // 6.4 MB   per (node, rel) counts
__device__ float d_pool[(size_t)G_CAP * P_DIM];
__device__ int   d_offs[G_CAP + 1];
// relation bucketing
__device__ int2  d_bedge[E_CAP];               // (src, dst) sorted by relation
__device__ int   d_bhist[R_CAP * NBLK_B];      // flat[rel*NBLK_B + blk]
__device__ int   d_boff [R_CAP * NBLK_B];
__device__ int   d_bstart[R_CAP];
__device__ int   d_bcnt  [R_CAP];

// ---------------- vector reductions (sm_90+) --------------------
__device__ __forceinline__ void red_add_v4(float* addr, float a, float b, float c, float d) {
    asm volatile("red.global.add.v4.f32 [%0], {%1, %2, %3, %4};"
                 :: "l"(addr), "f"(a), "f"(b), "f"(c), "f"(d) : "memory");
}
__device__ __forceinline__ void red_add_v2(float* addr, float a, float b) {
    asm volatile("red.global.add.v2.f32 [%0], {%1, %2};"
                 :: "l"(addr), "f"(a), "f"(b) : "memory");
}

#define GET4(v, kk) ((kk) == 0 ? (v).x : (kk) == 1 ? (v).y : (kk) == 2 ? (v).z : (v).w)

// ---------------- k_prep: zero counts, W = comp @ bases ----------
__global__ void k_prep(const float* __restrict__ comp, const float* __restrict__ bases,
                       int R, int NB, int N) {
    int tid = blockIdx.x * blockDim.x + threadIdx.x;
    int nth = gridDim.x * blockDim.x;
    int total_cnt = N * R;
    for (int i = tid; i < total_cnt; i += nth) d_cnt[i] = 0;
    int wtot = R * H_DIM * H_DIM;
    for (int i = tid; i < wtot; i += nth) {
        int r = i >> 12;          // / 4096
        int ij = i & 4095;
        float acc = 0.f;
        for (int b = 0; b < NB; b++)
            acc += comp[r * NB + b] * bases[b * 4096 + ij];
        d_W[i] = acc;
    }
}

// ---------------- k_scan: exclusive prefix of seq_lengths -------
__global__ void k_scan(const int* __restrict__ sl, int G) {
    __shared__ int s[1024];
    int t = threadIdx.x;
    s[t] = (t < G) ? sl[t] : 0;
    __syncthreads();
    for (int off = 1; off < 1024; off <<= 1) {
        int add = (t >= off) ? s[t - off] : 0;
        __syncthreads();
        s[t] += add;
        __syncthreads();
    }
    if (t == 0) d_offs[0] = 0;
    if (t < G) d_offs[t + 1] = s[t];
}

// ---------------- k_proj: y = x@w1_rel ; h = x@w1_root + b1 -----
// warp processes 4 nodes; weights (64KB) + per-warp 4-row x stage in dyn smem
__global__ void k_proj(const float* __restrict__ x, const float* __restrict__ w_rel,
                       const float* __restrict__ w_root, const float* __restrict__ b1,
                       int N) {
    extern __shared__ float sw[];   // [0,8192) w_rel, [8192,16384) w_root, then 512/warp stage
    for (int i = threadIdx.x; i < 8192; i += blockDim.x) {
        sw[i] = w_rel[i];
        sw[8192 + i] = w_root[i];
    }
    __syncthreads();
    int lane = threadIdx.x & 31;
    int wl   = threadIdx.x >> 5;
    int warp = (blockIdx.x * blockDim.x + threadIdx.x) >> 5;
    int nw   = (gridDim.x * blockDim.x) >> 5;
    float* sx = sw + 16384 + wl * 512;
    float bias0 = b1[2 * lane], bias1 = b1[2 * lane + 1];
    int nquad = (N + 3) >> 2;
    for (int q = warp; q < nquad; q += nw) {
        int n0 = 4 * q;
#pragma unroll
        for (int j = 0; j < 4; j++) {
            int n = n0 + j;
            float4 xv = (n < N) ? *(const float4*)(x + (size_t)n * F_DIM + 4 * lane)
                                : make_float4(0.f, 0.f, 0.f, 0.f);
            *(float4*)(sx + j * F_DIM + 4 * lane) = xv;
        }
        __syncwarp();
        float ya[4][2] = {}, ha[4][2] = {};
#pragma unroll
        for (int k4 = 0; k4 < F_DIM; k4 += 4) {
            float4 xb0 = *(const float4*)(sx + 0 * F_DIM + k4);
            float4 xb1 = *(const float4*)(sx + 1 * F_DIM + k4);
            float4 xb2 = *(const float4*)(sx + 2 * F_DIM + k4);
            float4 xb3 = *(const float4*)(sx + 3 * F_DIM + k4);
#pragma unroll
            for (int kk = 0; kk < 4; kk++) {
                float2 wr = *(const float2*)(sw + (k4 + kk) * 64 + 2 * lane);
                float2 wo = *(const float2*)(sw + 8192 + (k4 + kk) * 64 + 2 * lane);
                float x0 = GET4(xb0, kk), x1 = GET4(xb1, kk);
                float x2 = GET4(xb2, kk), x3 = GET4(xb3, kk);
                ya[0][0] += x0 * wr.x; ya[0][1] += x0 * wr.y;
                ha[0][0] += x0 * wo.x; ha[0][1] += x0 * wo.y;
                ya[1][0] += x1 * wr.x; ya[1][1] += x1 * wr.y;
                ha[1][0] += x1 * wo.x; ha[1][1] += x1 * wo.y;
                ya[2][0] += x2 * wr.x; ya[2][1] += x2 * wr.y;
                ha[2][0] += x2 * wo.x; ha[2][1] += x2 * wo.y;
                ya[3][0] += x3 * wr.x; ya[3][1] += x3 * wr.y;
                ha[3][0] += x3 * wo.x; ha[3][1] += x3 * wo.y;
            }
        }
#pragma unroll
        for (int j = 0; j < 4; j++) {
            int n = n0 + j;
            if (n < N) {
                *(float2*)(d_y + (size_t)n * H_DIM + 2 * lane) = make_float2(ya[j][0], ya[j][1]);
                *(float2*)(d_h + (size_t)n * H_DIM + 2 * lane) = make_float2(ha[j][0] + bias0, ha[j][1] + bias1);
            }
        }
        __syncwarp();
    }
}

// ---------------- k_hist: per (dst,rel) counts + per-block rel histogram
__global__ void k_hist(const int* __restrict__ ei, const int* __restrict__ et,
                       int E, int R, int chunk) {
    __shared__ int h[R_CAP];
    int t = threadIdx.x;
    if (t < R) h[t] = 0;
    __syncthreads();
    int s = blockIdx.x * chunk;
    int e_end = min(E, s + chunk);
    for (int e = s + t; e < e_end; e += blockDim.x) {
        int dst = ei[E + e];
        int r = et[e];
        atomicAdd(&d_cnt[(size_t)dst * R + r], 1);
        atomicAdd(&h[r], 1);
    }
    __syncthreads();
    if (t < R) d_bhist[t * NBLK_B + blockIdx.x] = h[t];
}

// ---------------- k_bscan: scan per-block histograms -> bucket offsets
__global__ void k_bscan(int R, int E) {
    __shared__ int ssum[1024];
    int t = threadIdx.x;
    int base = t * 8;             // 1024*8 = 8192 = R_CAP*NBLK_B
    int v[8];
    int s = 0;
#pragma unroll
    for (int i = 0; i < 8; i++) { v[i] = s; s += d_bhist[base + i]; }
    ssum[t] = s;
    __syncthreads();
    for (int off = 1; off < 1024; off <<= 1) {
        int add = (t >= off) ? ssum[t - off] : 0;
        __syncthreads();
        ssum[t] += add;
        __syncthreads();
    }
    int excl = ssum[t] - s;
#pragma unroll
    for (int i = 0; i < 8; i++) d_boff[base + i] = excl + v[i];
    if (t < R) {
        int chunks_per_rel = NBLK_B / 8;             // 64 threads-worth per relation
        int st = (t == 0) ? 0 : ssum[t * chunks_per_rel - 1];
        int en = ssum[(t + 1) * chunks_per_rel - 1];
        d_bstart[t] = st;
        d_bcnt[t] = en - st;
    }
}

// ---------------- k_scatter: write edges into relation buckets --
__global__ void k_scatter(const int* __restrict__ ei, const int* __restrict__ et,
                          int E, int R, int chunk) {
    __shared__ int c[R_CAP];
    int t = threadIdx.x;
    if (t < R) c[t] = d_boff[t * NBLK_B + blockIdx.x];
    __syncthreads();
    int s = blockIdx.x * chunk;
    int e_end = min(E, s + chunk);
    for (int e = s + t; e < e_end; e += blockDim.x) {
        int r = et[e];
        int pos = atomicAdd(&c[r], 1);
        d_bedge[pos] = make_int2(ei[e], ei[E + e]);
    }
}

// ---------------- k_agg1: h[dst] += y[src]*norm (16 thr/edge) ---
__global__ void k_agg1(const int* __restrict__ ei, const float* __restrict__ nrm, int E) {
    int t = blockIdx.x * blockDim.x + threadIdx.x;
    int e = t >> 4;
    if (e >= E) return;
    int sub = t & 15;
    int src = ei[e];
    int dst = ei[E + e];
    float w = nrm[e];
    float4 v = *(const float4*)(d_y + (size_t)src * H_DIM + sub * 4);
    red_add_v4(d_h + (size_t)dst * H_DIM + sub * 4, v.x * w, v.y * w, v.z * w, v.w * w);
}

// ---------------- k_oroot: o = h @ w2_root + b2 (4 nodes/warp) --
__global__ void k_oroot(const float* __restrict__ w2, const float* __restrict__ b2, int N) {
    __shared__ float sw[4096];
    __shared__ float sx[8][256];   // 4 nodes * 64 per warp
    for (int i = threadIdx.x; i < 4096; i += blockDim.x) sw[i] = w2[i];
    __syncthreads();
    int lane = threadIdx.x & 31;
    int wl   = threadIdx.x >> 5;
    int warp = (blockIdx.x * blockDim.x + threadIdx.x) >> 5;
    int nw   = (gridDim.x * blockDim.x) >> 5;
    float bias0 = b2[2 * lane], bias1 = b2[2 * lane + 1];
    int nquad = (N + 3) >> 2;
    for (int q = warp; q < nquad; q += nw) {
        int n0 = 4 * q;
#pragma unroll
        for (int j = 0; j < 4; j++) {
            int n = n0 + j;
            float2 hv = (n < N) ? *(const float2*)(d_h + (size_t)n * H_DIM + 2 * lane)
                                : make_float2(0.f, 0.f);
            *(float2*)(&sx[wl][j * 64 + 2 * lane]) = hv;
        }
        __syncwarp();
        float a[4][2] = {};
#pragma unroll
        for (int k4 = 0; k4 < H_DIM; k4 += 4) {
            float4 h0 = *(const float4*)(&sx[wl][0 + k4]);
            float4 h1 = *(const float4*)(&sx[wl][64 + k4]);
            float4 h2 = *(const float4*)(&sx[wl][128 + k4]);
            float4 h3 = *(const float4*)(&sx[wl][192 + k4]);
#pragma unroll
            for (int kk = 0; kk < 4; kk++) {
                float2 w = *(const float2*)(sw + (k4 + kk) * 64 + 2 * lane);
                float x0 = GET4(h0, kk), x1 = GET4(h1, kk);
                float x2 = GET4(h2, kk), x3 = GET4(h3, kk);
                a[0][0] += x0 * w.x; a[0][1] += x0 * w.y;
                a[1][0] += x1 * w.x; a[1][1] += x1 * w.y;
                a[2][0] += x2 * w.x; a[2][1] += x2 * w.y;
                a[3][0] += x3 * w.x; a[3][1] += x3 * w.y;
            }
        }
#pragma unroll
        for (int j = 0; j < 4; j++) {
            int n = n0 + j;
            if (n < N)
                *(float2*)(d_o + (size_t)n * H_DIM + 2 * lane) =
                    make_float2(a[j][0] + bias0, a[j][1] + bias1);
        }
        __syncwarp();
    }
}

// ---------------- k_rgcn2: bucketed, W in smem, 4 edges/warp ----
// o[dst] += (h[src] @ W[rel]) / cnt[dst,rel]
__global__ void k_rgcn2(int R) {
    __shared__ float sW[4096];
    __shared__ float shs[8][256];
    int rel = blockIdx.x % R;
    int chunk = blockIdx.x / R;            // 0..63
    int nchunk = gridDim.x / R;
    const float* __restrict__ W = d_W + (size_t)rel * 4096;
    for (int i = threadIdx.x; i < 1024; i += blockDim.x)
        *(float4*)(sW + 4 * i) = *(const float4*)(W + 4 * i);
    __syncthreads();
    int start = d_bstart[rel], cnt = d_bcnt[rel];
    int lane = threadIdx.x & 31, wl = threadIdx.x >> 5;
    int ngroups = (cnt + 3) >> 2;
    int wstride = nchunk * 8;
    for (int g = chunk * 8 + wl; g < ngroups; g += wstride) {
        int base = start + g * 4;
        int m = min(4, cnt - g * 4);
        int2 ev = make_int2(0, 0);
        if (lane < m) ev = d_bedge[base + lane];
        // stage h rows of the 4 src nodes
#pragma unroll
        for (int j = 0; j < 4; j++) {
            int sj = __shfl_sync(0xffffffffu, ev.x, j);
            *(float2*)(&shs[wl][j * 64 + 2 * lane]) =
                *(const float2*)(d_h + (size_t)sj * H_DIM + 2 * lane);
        }
        __syncwarp();
        float a[4][2] = {};
#pragma unroll
        for (int k4 = 0; k4 < H_DIM; k4 += 4) {
            float4 h0 = *(const float4*)(&shs[wl][0 + k4]);
            float4 h1 = *(const float4*)(&shs[wl][64 + k4]);
            float4 h2 = *(const float4*)(&shs[wl][128 + k4]);
            float4 h3 = *(const float4*)(&shs[wl][192 + k4]);
#pragma unroll
            for (int kk = 0; kk < 4; kk++) {
                float2 w = *(const float2*)(&sW[(k4 + kk) * 64 + 2 * lane]);
                float x0 = GET4(h0, kk), x1 = GET4(h1, kk);
                float x2 = GET4(h2, kk), x3 = GET4(h3, kk);
                a[0][0] += x0 * w.x; a[0][1] += x0 * w.y;
                a[1][0] += x1 * w.x; a[1][1] += x1 * w.y;
                a[2][0] += x2 * w.x; a[2][1] += x2 * w.y;
                a[3][0] += x3 * w.x; a[3][1] += x3 * w.y;
            }
        }
#pragma unroll
        for (int j = 0; j < 4; j++) {
            if (j < m) {
                int dj = __shfl_sync(0xffffffffu, ev.y, j);
                int c = d_cnt[(size_t)dj * R + rel];
                float inv = 1.f / (float)(c > 1 ? c : 1);
                red_add_v2(d_o + (size_t)dj * H_DIM + 2 * lane,
                           a[j][0] * inv, a[j][1] * inv);
            }
        }
        __syncwarp();
    }
}

// ---------------- k_pool: per-graph sum + max -------------------
__global__ void k_pool(const float* __restrict__ x, int G) {
    int g = blockIdx.x;
    int s = d_offs[g], e = d_offs[g + 1];
    int d = threadIdx.x;                 // 192 threads
    float sum = 0.f, mx = -INFINITY;
    if (d < F_DIM) {
#pragma unroll 4
        for (int n = s; n < e; n++) {
            float v = x[(size_t)n * F_DIM + d];
            sum += v; mx = fmaxf(mx, v);
        }
    } else {
        int dd = d - F_DIM;
#pragma unroll 4
        for (int n = s; n < e; n++) {
            float v = d_o[(size_t)n * H_DIM + dd];
            sum += v; mx = fmaxf(mx, v);
        }
    }
    d_pool[(size_t)g * P_DIM + d] = sum;
    d_pool[(size_t)g * P_DIM + 192 + d] = mx;
}

// ---------------- k_head: linear->relu->linear->log_softmax -----
__global__ void k_head(const float* __restrict__ lin_w, const float* __restrict__ lin_b,
                       const float* __restrict__ fc_w, const float* __restrict__ fc_b,
                       float* __restrict__ out, int G) {
    __shared__ float sp[P_DIM];
    __shared__ float hid[H_DIM];
    __shared__ float lg[C_DIM];
    __shared__ float lse;
    int g = blockIdx.x, t = threadIdx.x;   // 64 threads
    for (int i = t; i < P_DIM; i += 64) sp[i] = d_pool[(size_t)g * P_DIM + i];
    __syncthreads();
    float acc = lin_b[t];
#pragma unroll 8
    for (int k = 0; k < P_DIM; k++) acc += sp[k] * lin_w[k * H_DIM + t];
    hid[t] = fmaxf(acc, 0.f);
    __syncthreads();
    if (t < C_DIM) {
        float a = fc_b[t];
#pragma unroll
        for (int k = 0; k < H_DIM; k++) a += hid[k] * fc_w[k * C_DIM + t];
        lg[t] = a;
    }
    __syncthreads();
    if (t == 0) {
        float m = -INFINITY;
        for (int j = 0; j < C_DIM; j++) m = fmaxf(m, lg[j]);
        float s2 = 0.f;
        for (int j = 0; j < C_DIM; j++) s2 += expf(lg[j] - m);
        lse = m + logf(s2);
    }
    __syncthreads();
    if (t < C_DIM) out[(size_t)g * C_DIM + t] = lg[t] - lse;
}

// ---------------- launch ----------------------------------------
extern "C" void kernel_launch(void* const* d_in, const int* in_sizes, int n_in,
                              void* d_out, int out_size) {
    // avec may or may not be materialized as an input; detect by count.
    int o = (n_in >= 17) ? 0 : -1;
    const float* x       = (const float*)d_in[0];
    const int*   ei      = (const int*)d_in[1];
    const float* enorm   = (const float*)d_in[2];
    const int*   etype   = (const int*)d_in[3];
    const int*   seql    = (const int*)d_in[4];
    const float* w1_rel  = (const float*)d_in[6 + o];
    const float* w1_root = (const float*)d_in[7 + o];
    const float* b1      = (const float*)d_in[8 + o];
    const float* bases   = (const float*)d_in[9 + o];
    const float* comp    = (const float*)d_in[10 + o];
    const float* w2      = (const float*)d_in[11 + o];
    const float* b2      = (const float*)d_in[12 + o];
    const float* lin_w   = (const float*)d_in[13 + o];
    const float* lin_b   = (const float*)d_in[14 + o];
    const float* fc_w    = (const float*)d_in[15 + o];
    const float* fc_b    = (const float*)d_in[16 + o];

    int N  = in_sizes[0] / F_DIM;
    int E  = in_sizes[2];
    int G  = in_sizes[4];
    int NB = in_sizes[9 + o] / (H_DIM * H_DIM);
    int R  = in_sizes[10 + o] / NB;
    float* out = (float*)d_out;
    (void)out_size;

    cudaFuncSetAttribute(k_proj, cudaFuncAttributeMaxDynamicSharedMemorySize, 81920);

    int chunk = (E + NBLK_B - 1) / NBLK_B;

    k_prep<<<2048, 256>>>(comp, bases, R, NB, N);
    k_scan<<<1, 1024>>>(seql, G);
    k_proj<<<444, 256, 81920>>>(x, w1_rel, w1_root, b1, N);
    k_hist<<<NBLK_B, 256>>>(ei, etype, E, R, chunk);
    k_bscan<<<1, 1024>>>(R, E);
    k_scatter<<<NBLK_B, 256>>>(ei, etype, E, R, chunk);
    {
        long long t = (long long)E * 16;
        k_agg1<<<(int)((t + 255) / 256), 256>>>(ei, enorm, E);
    }
    k_oroot<<<592, 256>>>(w2, b2, N);
    k_rgcn2<<<R * 64, 256>>>(R);
    k_pool<<<G, 192>>>(x, G);
    k_head<<<G, 64>>>(lin_w, lin_b, fc_w, fc_b, out, G);
}

// round 7
// speedup vs baseline: 1.5235x; 1.0140x over previous
#include <cuda_runtime.h>
#include <cuda_bf16.h>
#include <math.h>

// ---------------- compile-time architecture dims ----------------
#define F_DIM 128
#define H_DIM 64
#define C_DIM 10
#define P_DIM 384           // 2*(F+H)
#define N_CAP 100000
#define R_CAP 16
#define G_CAP 1024
#define E_CAP 1000000
#define NBLK_B 512          // blocks for hist/scatter passes

// ---------------- scratch (static device arrays; no allocs) -----
__device__ float d_W[R_CAP * H_DIM * H_DIM];   // 256 KB  [r][k][n]
__device__ float d_y[(size_t)N_CAP * H_DIM];   // 25.6 MB  x @ w1_rel
__device__ float d_h[(size_t)N_CAP * H_DIM];   // 25.6 MB  node hidden
__device__ float d_o[(size_t)N_CAP * H_DIM];   // 25.6 MB  rgcn out
__device__ int   d_cnt[(size_t)N_CAP * R_CAP]; // 6.4 MB   per (node, rel) counts
__device__ float d_pool[(size_t)G_CAP * P_DIM];
__device__ int   d_offs[G_CAP + 1];
// relation bucketing
__device__ int2  d_bedge[E_CAP];               // (src, dst) sorted by relation
__device__ int   d_bhist[R_CAP * NBLK_B];      // flat[rel*NBLK_B + blk]
__device__ int   d_boff [R_CAP * NBLK_B];
__device__ int   d_bstart[R_CAP];
__device__ int   d_bcnt  [R_CAP];

// ---------------- vector reductions (sm_90+) --------------------
__device__ __forceinline__ void red_add_v4(float* addr, float a, float b, float c, float d) {
    asm volatile("red.global.add.v4.f32 [%0], {%1, %2, %3, %4};"
                 :: "l"(addr), "f"(a), "f"(b), "f"(c), "f"(d) : "memory");
}
__device__ __forceinline__ void red_add_v2(float* addr, float a, float b) {
    asm volatile("red.global.add.v2.f32 [%0], {%1, %2};"
                 :: "l"(addr), "f"(a), "f"(b) : "memory");
}

// ---------------- packed f32x2 helpers (sm_103a FFMA2) ----------
typedef unsigned long long u64;
__device__ __forceinline__ void ffma2(u64& acc, u64 a, u64 b) {
    asm("fma.rn.f32x2 %0, %1, %2, %0;" : "+l"(acc) : "l"(a), "l"(b));
}
__device__ __forceinline__ u64 pack2(float lo, float hi) {
    u64 r;
    asm("mov.b64 %0, {%1, %2};" : "=l"(r) : "f"(lo), "f"(hi));
    return r;
}
__device__ __forceinline__ u64 splat2(float w) {
    u64 r;
    asm("mov.b64 %0, {%1, %1};" : "=l"(r) : "f"(w));
    return r;
}
__device__ __forceinline__ void unpack2(u64 v, float& lo, float& hi) {
    asm("mov.b64 {%0, %1}, %2;" : "=f"(lo), "=f"(hi) : "l"(v));
}

// ---------------- k_prep: zero counts, W = comp @ bases ----------
__global__ void k_prep(const float* __restrict__ comp, const float* __restrict__ bases,
                       int R, int NB, int N) {
    int tid = blockIdx.x * blockDim.x + threadIdx.x;
    int nth = gridDim.x * blockDim.x;
    int total_cnt = N * R;
    for (int i = tid; i < total_cnt; i += nth) d_cnt[i] = 0;
    int wtot = R * H_DIM * H_DIM;
    for (int i = tid; i < wtot; i += nth) {
        int r = i >> 12;          // / 4096
        int ij = i & 4095;
        float acc = 0.f;
        for (int b = 0; b < NB; b++)
            acc += comp[r * NB + b] * bases[b * 4096 + ij];
        d_W[i] = acc;
    }
}

// ---------------- k_scan: exclusive prefix of seq_lengths -------
__global__ void k_scan(const int* __restrict__ sl, int G) {
    __shared__ int s[1024];
    int t = threadIdx.x;
    s[t] = (t < G) ? sl[t] : 0;
    __syncthreads();
    for (int off = 1; off < 1024; off <<= 1) {
        int add = (t >= off) ? s[t - off] : 0;
        __syncthreads();
        s[t] += add;
        __syncthreads();
    }
    if (t == 0) d_offs[0] = 0;
    if (t < G) d_offs[t + 1] = s[t];
}

// ---------------- k_proj: y = x@w1_rel ; h = x@w1_root + b1 -----
// 4 nodes/warp as 2 packed node-pairs; FFMA2 inner loop.
// dyn smem: [0,8192) w_rel, [8192,16384) w_root, then u64 pair-stage 2KB/warp
__global__ void k_proj(const float* __restrict__ x, const float* __restrict__ w_rel,
                       const float* __restrict__ w_root, const float* __restrict__ b1,
                       int N) {
    extern __shared__ float sw[];
    u64* spair = (u64*)(sw + 16384);
    for (int i = threadIdx.x; i < 8192; i += blockDim.x) {
        sw[i] = w_rel[i];
        sw[8192 + i] = w_root[i];
    }
    __syncthreads();
    int lane = threadIdx.x & 31;
    int wl   = threadIdx.x >> 5;
    int warp = (blockIdx.x * blockDim.x + threadIdx.x) >> 5;
    int nw   = (gridDim.x * blockDim.x) >> 5;
    u64* sx = spair + wl * 256;       // [jp*128 + k]
    float bias0 = b1[2 * lane], bias1 = b1[2 * lane + 1];
    int nquad = (N + 3) >> 2;
    for (int q = warp; q < nquad; q += nw) {
        int n0 = 4 * q;
#pragma unroll
        for (int jp = 0; jp < 2; jp++) {
            int na = n0 + 2 * jp, nb = na + 1;
#pragma unroll
            for (int kb = 0; kb < 4; kb++) {
                int k = kb * 32 + lane;
                float f0 = (na < N) ? x[(size_t)na * F_DIM + k] : 0.f;
                float f1 = (nb < N) ? x[(size_t)nb * F_DIM + k] : 0.f;
                sx[jp * 128 + k] = pack2(f0, f1);
            }
        }
        __syncwarp();
        u64 ya[2][2] = {{0, 0}, {0, 0}};
        u64 ha[2][2] = {{0, 0}, {0, 0}};
#pragma unroll 8
        for (int k = 0; k < F_DIM; k++) {
            float2 wr = *(const float2*)(sw + k * 64 + 2 * lane);
            float2 wo = *(const float2*)(sw + 8192 + k * 64 + 2 * lane);
            u64 xp0 = sx[k];
            u64 xp1 = sx[128 + k];
            u64 Wrx = splat2(wr.x), Wry = splat2(wr.y);
            u64 Wox = splat2(wo.x), Woy = splat2(wo.y);
            ffma2(ya[0][0], xp0, Wrx); ffma2(ya[0][1], xp0, Wry);
            ffma2(ha[0][0], xp0, Wox); ffma2(ha[0][1], xp0, Woy);
            ffma2(ya[1][0], xp1, Wrx); ffma2(ya[1][1], xp1, Wry);
            ffma2(ha[1][0], xp1, Wox); ffma2(ha[1][1], xp1, Woy);
        }
#pragma unroll
        for (int jp = 0; jp < 2; jp++) {
            int na = n0 + 2 * jp, nb = na + 1;
            float y0l, y0h, y1l, y1h, h0l, h0h, h1l, h1h;
            unpack2(ya[jp][0], y0l, y0h);
            unpack2(ya[jp][1], y1l, y1h);
            unpack2(ha[jp][0], h0l, h0h);
            unpack2(ha[jp][1], h1l, h1h);
            if (na < N) {
                *(float2*)(d_y + (size_t)na * H_DIM + 2 * lane) = make_float2(y0l, y1l);
                *(float2*)(d_h + (size_t)na * H_DIM + 2 * lane) = make_float2(h0l + bias0, h1l + bias1);
            }
            if (nb < N) {
                *(float2*)(d_y + (size_t)nb * H_DIM + 2 * lane) = make_float2(y0h, y1h);
                *(float2*)(d_h + (size_t)nb * H_DIM + 2 * lane) = make_float2(h0h + bias0, h1h + bias1);
            }
        }
        __syncwarp();
    }
}

// ---------------- k_hist: per (dst,rel) counts + per-block rel histogram
__global__ void k_hist(const int* __restrict__ ei, const int* __restrict__ et,
                       int E, int R, int chunk) {
    __shared__ int h[R_CAP];
    int t = threadIdx.x;
    if (t < R) h[t] = 0;
    __syncthreads();
    int s = blockIdx.x * chunk;
    int e_end = min(E, s + chunk);
    for (int e = s + t; e < e_end; e += blockDim.x) {
        int dst = ei[E + e];
        int r = et[e];
        atomicAdd(&d_cnt[(size_t)dst * R + r], 1);
        atomicAdd(&h[r], 1);
    }
    __syncthreads();
    if (t < R) d_bhist[t * NBLK_B + blockIdx.x] = h[t];
}

// ---------------- k_bscan: scan per-block histograms -> bucket offsets
__global__ void k_bscan(int R, int E) {
    __shared__ int ssum[1024];
    int t = threadIdx.x;
    int base = t * 8;             // 1024*8 = 8192 = R_CAP*NBLK_B
    int v[8];
    int s = 0;
#pragma unroll
    for (int i = 0; i < 8; i++) { v[i] = s; s += d_bhist[base + i]; }
    ssum[t] = s;
    __syncthreads();
    for (int off = 1; off < 1024; off <<= 1) {
        int add = (t >= off) ? ssum[t - off] : 0;
        __syncthreads();
        ssum[t] += add;
        __syncthreads();
    }
    int excl = ssum[t] - s;
#pragma unroll
    for (int i = 0; i < 8; i++) d_boff[base + i] = excl + v[i];
    if (t < R) {
        int chunks_per_rel = NBLK_B / 8;             // 64 threads-worth per relation
        int st = (t == 0) ? 0 : ssum[t * chunks_per_rel - 1];
        int en = ssum[(t + 1) * chunks_per_rel - 1];
        d_bstart[t] = st;
        d_bcnt[t] = en - st;
    }
}

// ---------------- k_scatter: write edges into relation buckets --
__global__ void k_scatter(const int* __restrict__ ei, const int* __restrict__ et,
                          int E, int R, int chunk) {
    __shared__ int c[R_CAP];
    int t = threadIdx.x;
    if (t < R) c[t] = d_boff[t * NBLK_B + blockIdx.x];
    __syncthreads();
    int s = blockIdx.x * chunk;
    int e_end = min(E, s + chunk);
    for (int e = s + t; e < e_end; e += blockDim.x) {
        int r = et[e];
        int pos = atomicAdd(&c[r], 1);
        d_bedge[pos] = make_int2(ei[e], ei[E + e]);
    }
}

// ---------------- k_agg1: h[dst] += y[src]*norm (16 thr/edge) ---
__global__ void k_agg1(const int* __restrict__ ei, const float* __restrict__ nrm, int E) {
    int t = blockIdx.x * blockDim.x + threadIdx.x;
    int e = t >> 4;
    if (e >= E) return;
    int sub = t & 15;
    int src = ei[e];
    int dst = ei[E + e];
    float w = nrm[e];
    float4 v = *(const float4*)(d_y + (size_t)src * H_DIM + sub * 4);
    red_add_v4(d_h + (size_t)dst * H_DIM + sub * 4, v.x * w, v.y * w, v.z * w, v.w * w);
}

// ---------------- k_oroot: o = h @ w2_root + b2 (FFMA2, 4 nodes/warp)
__global__ void k_oroot(const float* __restrict__ w2, const float* __restrict__ b2, int N) {
    __shared__ float sw[4096];
    __shared__ u64 sp2[8][128];       // per warp: [jp*64 + k]
    for (int i = threadIdx.x; i < 4096; i += blockDim.x) sw[i] = w2[i];
    __syncthreads();
    int lane = threadIdx.x & 31;
    int wl   = threadIdx.x >> 5;
    int warp = (blockIdx.x * blockDim.x + threadIdx.x) >> 5;
    int nw   = (gridDim.x * blockDim.x) >> 5;
    float bias0 = b2[2 * lane], bias1 = b2[2 * lane + 1];
    int nquad = (N + 3) >> 2;
    for (int q = warp; q < nquad; q += nw) {
        int n0 = 4 * q;
#pragma unroll
        for (int jp = 0; jp < 2; jp++) {
            int na = n0 + 2 * jp, nb = na + 1;
            int kb = lane & 1 ? 32 : 0;        // 2 halves per two lane groups? keep simple:
            (void)kb;
#pragma unroll
            for (int h2 = 0; h2 < 2; h2++) {
                int k = h2 * 32 + lane;
                float f0 = (na < N) ? d_h[(size_t)na * H_DIM + k] : 0.f;
                float f1 = (nb < N) ? d_h[(size_t)nb * H_DIM + k] : 0.f;
                sp2[wl][jp * 64 + k] = pack2(f0, f1);
            }
        }
        __syncwarp();
        u64 a[2][2] = {{0, 0}, {0, 0}};
#pragma unroll 8
        for (int k = 0; k < H_DIM; k++) {
            float2 w = *(const float2*)(sw + k * 64 + 2 * lane);
            u64 xp0 = sp2[wl][k];
            u64 xp1 = sp2[wl][64 + k];
            u64 Wx = splat2(w.x), Wy = splat2(w.y);
            ffma2(a[0][0], xp0, Wx); ffma2(a[0][1], xp0, Wy);
            ffma2(a[1][0], xp1, Wx); ffma2(a[1][1], xp1, Wy);
        }
#pragma unroll
        for (int jp = 0; jp < 2; jp++) {
            int na = n0 + 2 * jp, nb = na + 1;
            float a0l, a0h, a1l, a1h;
            unpack2(a[jp][0], a0l, a0h);
            unpack2(a[jp][1], a1l, a1h);
            if (na < N)
                *(float2*)(d_o + (size_t)na * H_DIM + 2 * lane) =
                    make_float2(a0l + bias0, a1l + bias1);
            if (nb < N)
                *(float2*)(d_o + (size_t)nb * H_DIM + 2 * lane) =
                    make_float2(a0h + bias0, a1h + bias1);
        }
        __syncwarp();
    }
}

// ---------------- k_rgcn2: bucketed, W in smem, 4 edges/warp, FFMA2
// o[dst] += (h[src] @ W[rel]) / cnt[dst,rel]
__global__ void k_rgcn2(int R) {
    __shared__ float sW[4096];
    __shared__ u64 shp[8][128];       // per warp: [jp*64 + k] packed src pairs
    int rel = blockIdx.x % R;
    int chunk = blockIdx.x / R;
    int nchunk = gridDim.x / R;
    const float* __restrict__ W = d_W + (size_t)rel * 4096;
    for (int i = threadIdx.x; i < 1024; i += blockDim.x)
        *(float4*)(sW + 4 * i) = *(const float4*)(W + 4 * i);
    __syncthreads();
    int start = d_bstart[rel], cnt = d_bcnt[rel];
    int lane = threadIdx.x & 31, wl = threadIdx.x >> 5;
    int ngroups = (cnt + 3) >> 2;
    int wstride = nchunk * 8;
    for (int g = chunk * 8 + wl; g < ngroups; g += wstride) {
        int base = start + g * 4;
        int m = min(4, cnt - g * 4);
        int2 ev = make_int2(0, 0);
        if (lane < m) ev = d_bedge[base + lane];
        // stage packed src pairs: shp[wl][jp*64+k] = (h[s_{2jp}][k], h[s_{2jp+1}][k])
#pragma unroll
        for (int jp = 0; jp < 2; jp++) {
            int s0 = __shfl_sync(0xffffffffu, ev.x, 2 * jp);
            int s1 = __shfl_sync(0xffffffffu, ev.x, 2 * jp + 1);
#pragma unroll
            for (int h2 = 0; h2 < 2; h2++) {
                int k = h2 * 32 + lane;
                float f0 = d_h[(size_t)s0 * H_DIM + k];
                float f1 = d_h[(size_t)s1 * H_DIM + k];
                shp[wl][jp * 64 + k] = pack2(f0, f1);
            }
        }
        __syncwarp();
        u64 a[2][2] = {{0, 0}, {0, 0}};
#pragma unroll 8
        for (int k = 0; k < H_DIM; k++) {
            float2 w = *(const float2*)(&sW[k * 64 + 2 * lane]);
            u64 xp0 = shp[wl][k];
            u64 xp1 = shp[wl][64 + k];
            u64 Wx = splat2(w.x), Wy = splat2(w.y);
            ffma2(a[0][0], xp0, Wx); ffma2(a[0][1], xp0, Wy);
            ffma2(a[1][0], xp1, Wx); ffma2(a[1][1], xp1, Wy);
        }
#pragma unroll
        for (int jp = 0; jp < 2; jp++) {
            float a0l, a0h, a1l, a1h;
            unpack2(a[jp][0], a0l, a0h);
            unpack2(a[jp][1], a1l, a1h);
            int j0 = 2 * jp, j1 = 2 * jp + 1;
            if (j0 < m) {
                int dj = __shfl_sync(0xffffffffu, ev.y, j0);
                int c = d_cnt[(size_t)dj * R + rel];
                float inv = 1.f / (float)(c > 1 ? c : 1);
                red_add_v2(d_o + (size_t)dj * H_DIM + 2 * lane, a0l * inv, a1l * inv);
            }
            if (j1 < m) {
                int dj = __shfl_sync(0xffffffffu, ev.y, j1);
                int c = d_cnt[(size_t)dj * R + rel];
                float inv = 1.f / (float)(c > 1 ? c : 1);
                red_add_v2(d_o + (size_t)dj * H_DIM + 2 * lane, a0h * inv, a1h * inv);
            }
        }
        __syncwarp();
    }
}

// ---------------- k_pool: per-graph sum + max -------------------
__global__ void k_pool(const float* __restrict__ x, int G) {
    int g = blockIdx.x;
    int s = d_offs[g], e = d_offs[g + 1];
    int d = threadIdx.x;                 // 192 threads
    float sum = 0.f, mx = -INFINITY;
    if (d < F_DIM) {
#pragma unroll 4
        for (int n = s; n < e; n++) {
            float v = x[(size_t)n * F_DIM + d];
            sum += v; mx = fmaxf(mx, v);
        }
    } else {
        int dd = d - F_DIM;
#pragma unroll 4
        for (int n = s; n < e; n++) {
            float v = d_o[(size_t)n * H_DIM + dd];
            sum += v; mx = fmaxf(mx, v);
        }
    }
    d_pool[(size_t)g * P_DIM + d] = sum;
    d_pool[(size_t)g * P_DIM + 192 + d] = mx;
}

// ---------------- k_head: linear->relu->linear->log_softmax -----
__global__ void k_head(const float* __restrict__ lin_w, const float* __restrict__ lin_b,
                       const float* __restrict__ fc_w, const float* __restrict__ fc_b,
                       float* __restrict__ out, int G) {
    __shared__ float sp[P_DIM];
    __shared__ float hid[H_DIM];
    __shared__ float lg[C_DIM];
    __shared__ float lse;
    int g = blockIdx.x, t = threadIdx.x;   // 64 threads
    for (int i = t; i < P_DIM; i += 64) sp[i] = d_pool[(size_t)g * P_DIM + i];
    __syncthreads();
    float acc = lin_b[t];
#pragma unroll 8
    for (int k = 0; k < P_DIM; k++) acc += sp[k] * lin_w[k * H_DIM + t];
    hid[t] = fmaxf(acc, 0.f);
    __syncthreads();
    if (t < C_DIM) {
        float a = fc_b[t];
#pragma unroll
        for (int k = 0; k < H_DIM; k++) a += hid[k] * fc_w[k * C_DIM + t];
        lg[t] = a;
    }
    __syncthreads();
    if (t == 0) {
        float m = -INFINITY;
        for (int j = 0; j < C_DIM; j++) m = fmaxf(m, lg[j]);
        float s2 = 0.f;
        for (int j = 0; j < C_DIM; j++) s2 += expf(lg[j] - m);
        lse = m + logf(s2);
    }
    __syncthreads();
    if (t < C_DIM) out[(size_t)g * C_DIM + t] = lg[t] - lse;
}

// ---------------- launch ----------------------------------------
extern "C" void kernel_launch(void* const* d_in, const int* in_sizes, int n_in,
                              void* d_out, int out_size) {
    // avec may or may not be materialized as an input; detect by count.
    int o = (n_in >= 17) ? 0 : -1;
    const float* x       = (const float*)d_in[0];
    const int*   ei      = (const int*)d_in[1];
    const float* enorm   = (const float*)d_in[2];
    const int*   etype   = (const int*)d_in[3];
    const int*   seql    = (const int*)d_in[4];
    const float* w1_rel  = (const float*)d_in[6 + o];
    const float* w1_root = (const float*)d_in[7 + o];
    const float* b1      = (const float*)d_in[8 + o];
    const float* bases   = (const float*)d_in[9 + o];
    const float* comp    = (const float*)d_in[10 + o];
    const float* w2      = (const float*)d_in[11 + o];
    const float* b2      = (const float*)d_in[12 + o];
    const float* lin_w   = (const float*)d_in[13 + o];
    const float* lin_b   = (const float*)d_in[14 + o];
    const float* fc_w    = (const float*)d_in[15 + o];
    const float* fc_b    = (const float*)d_in[16 + o];

    int N  = in_sizes[0] / F_DIM;
    int E  = in_sizes[2];
    int G  = in_sizes[4];
    int NB = in_sizes[9 + o] / (H_DIM * H_DIM);
    int R  = in_sizes[10 + o] / NB;
    float* out = (float*)d_out;
    (void)out_size;

    cudaFuncSetAttribute(k_proj, cudaFuncAttributeMaxDynamicSharedMemorySize, 81920);

    int chunk = (E + NBLK_B - 1) / NBLK_B;

    k_prep<<<2048, 256>>>(comp, bases, R, NB, N);
    k_scan<<<1, 1024>>>(seql, G);
    k_proj<<<444, 256, 81920>>>(x, w1_rel, w1_root, b1, N);
    k_hist<<<NBLK_B, 256>>>(ei, etype, E, R, chunk);
    k_bscan<<<1, 1024>>>(R, E);
    k_scatter<<<NBLK_B, 256>>>(ei, etype, E, R, chunk);
    {
        long long t = (long long)E * 16;
        k_agg1<<<(int)((t + 255) / 256), 256>>>(ei, enorm, E);
    }
    k_oroot<<<592, 256>>>(w2, b2, N);
    k_rgcn2<<<R * 64, 256>>>(R);
    k_pool<<<G, 192>>>(x, G);
    k_head<<<G, 64>>>(lin_w, lin_b, fc_w, fc_b, out, G);
}

// round 8
// speedup vs baseline: 1.7168x; 1.1269x over previous
#include <cuda_runtime.h>
#include <cuda_bf16.h>
#include <math.h>

// ---------------- compile-time architecture dims ----------------
#define F_DIM 128
#define H_DIM 64
#define C_DIM 10
#define P_DIM 384           // 2*(F+H)
#define N_CAP 100000
#define R_CAP 16
#define G_CAP 1024
#define E_CAP 1000000
#define NBLK_B 512          // blocks for hist/scatter passes
#define DSCAN_B 256         // blocks for dst scan

// ---------------- scratch (static device arrays; no allocs) -----
__device__ float d_W[R_CAP * H_DIM * H_DIM];   // 256 KB  [r][k][n]
__device__ float d_y[(size_t)N_CAP * H_DIM];   // 25.6 MB  x @ w1_rel
__device__ float d_h[(size_t)N_CAP * H_DIM];   // 25.6 MB  node hidden
__device__ float d_o[(size_t)N_CAP * H_DIM];   // 25.6 MB  rgcn out
__device__ int   d_cnt[(size_t)N_CAP * R_CAP]; // 6.4 MB   per (node, rel) counts
__device__ float d_pool[(size_t)G_CAP * P_DIM];
__device__ int   d_offs[G_CAP + 1];
// relation bucketing (for k_rgcn2)
__device__ int2  d_bedge[E_CAP];               // (src, dst) sorted by relation
__device__ int   d_bhist[R_CAP * NBLK_B];
__device__ int   d_boff [R_CAP * NBLK_B];
__device__ int   d_bstart[R_CAP];
__device__ int   d_bcnt  [R_CAP];
// dst bucketing (for k_agg1b, atomic-free aggregation)
__device__ int2  d_dedge[E_CAP];               // (src, nrm_bits) sorted by dst
__device__ int   d_dcnt[N_CAP];
__device__ int   d_doff[N_CAP + 1];
__device__ int   d_dcur[N_CAP];
__device__ int   d_dpartial[DSCAN_B];

// ---------------- vector reductions (sm_90+) --------------------
__device__ __forceinline__ void red_add_v2(float* addr, float a, float b) {
    asm volatile("red.global.add.v2.f32 [%0], {%1, %2};"
                 :: "l"(addr), "f"(a), "f"(b) : "memory");
}

// ---------------- packed f32x2 helpers (sm_103a FFMA2) ----------
typedef unsigned long long u64;
__device__ __forceinline__ void ffma2(u64& acc, u64 a, u64 b) {
    asm("fma.rn.f32x2 %0, %1, %2, %0;" : "+l"(acc) : "l"(a), "l"(b));
}
__device__ __forceinline__ u64 pack2(float lo, float hi) {
    u64 r;
    asm("mov.b64 %0, {%1, %2};" : "=l"(r) : "f"(lo), "f"(hi));
    return r;
}
__device__ __forceinline__ u64 splat2(float w) {
    u64 r;
    asm("mov.b64 %0, {%1, %1};" : "=l"(r) : "f"(w));
    return r;
}
__device__ __forceinline__ void unpack2(u64 v, float& lo, float& hi) {
    asm("mov.b64 {%0, %1}, %2;" : "=f"(lo), "=f"(hi) : "l"(v));
}

// ---------------- k_prep: zero counts, W = comp @ bases ----------
__global__ void k_prep(const float* __restrict__ comp, const float* __restrict__ bases,
                       int R, int NB, int N) {
    int tid = blockIdx.x * blockDim.x + threadIdx.x;
    int nth = gridDim.x * blockDim.x;
    int total_cnt = N * R;
    for (int i = tid; i < total_cnt; i += nth) d_cnt[i] = 0;
    for (int i = tid; i < N; i += nth) d_dcnt[i] = 0;
    int wtot = R * H_DIM * H_DIM;
    for (int i = tid; i < wtot; i += nth) {
        int r = i >> 12;          // / 4096
        int ij = i & 4095;
        float acc = 0.f;
        for (int b = 0; b < NB; b++)
            acc += comp[r * NB + b] * bases[b * 4096 + ij];
        d_W[i] = acc;
    }
}

// ---------------- k_scan: exclusive prefix of seq_lengths -------
__global__ void k_scan(const int* __restrict__ sl, int G) {
    __shared__ int s[1024];
    int t = threadIdx.x;
    s[t] = (t < G) ? sl[t] : 0;
    __syncthreads();
    for (int off = 1; off < 1024; off <<= 1) {
        int add = (t >= off) ? s[t - off] : 0;
        __syncthreads();
        s[t] += add;
        __syncthreads();
    }
    if (t == 0) d_offs[0] = 0;
    if (t < G) d_offs[t + 1] = s[t];
}

// ---------------- k_proj: y = x@w1_rel ; h = x@w1_root + b1 -----
__global__ void k_proj(const float* __restrict__ x, const float* __restrict__ w_rel,
                       const float* __restrict__ w_root, const float* __restrict__ b1,
                       int N) {
    extern __shared__ float sw[];
    u64* spair = (u64*)(sw + 16384);
    for (int i = threadIdx.x; i < 8192; i += blockDim.x) {
        sw[i] = w_rel[i];
        sw[8192 + i] = w_root[i];
    }
    __syncthreads();
    int lane = threadIdx.x & 31;
    int wl   = threadIdx.x >> 5;
    int warp = (blockIdx.x * blockDim.x + threadIdx.x) >> 5;
    int nw   = (gridDim.x * blockDim.x) >> 5;
    u64* sx = spair + wl * 256;       // [jp*128 + k]
    float bias0 = b1[2 * lane], bias1 = b1[2 * lane + 1];
    int nquad = (N + 3) >> 2;
    for (int q = warp; q < nquad; q += nw) {
        int n0 = 4 * q;
#pragma unroll
        for (int jp = 0; jp < 2; jp++) {
            int na = n0 + 2 * jp, nb = na + 1;
#pragma unroll
            for (int kb = 0; kb < 4; kb++) {
                int k = kb * 32 + lane;
                float f0 = (na < N) ? x[(size_t)na * F_DIM + k] : 0.f;
                float f1 = (nb < N) ? x[(size_t)nb * F_DIM + k] : 0.f;
                sx[jp * 128 + k] = pack2(f0, f1);
            }
        }
        __syncwarp();
        u64 ya[2][2] = {{0, 0}, {0, 0}};
        u64 ha[2][2] = {{0, 0}, {0, 0}};
#pragma unroll 8
        for (int k = 0; k < F_DIM; k++) {
            float2 wr = *(const float2*)(sw + k * 64 + 2 * lane);
            float2 wo = *(const float2*)(sw + 8192 + k * 64 + 2 * lane);
            u64 xp0 = sx[k];
            u64 xp1 = sx[128 + k];
            u64 Wrx = splat2(wr.x), Wry = splat2(wr.y);
            u64 Wox = splat2(wo.x), Woy = splat2(wo.y);
            ffma2(ya[0][0], xp0, Wrx); ffma2(ya[0][1], xp0, Wry);
            ffma2(ha[0][0], xp0, Wox); ffma2(ha[0][1], xp0, Woy);
            ffma2(ya[1][0], xp1, Wrx); ffma2(ya[1][1], xp1, Wry);
            ffma2(ha[1][0], xp1, Wox); ffma2(ha[1][1], xp1, Woy);
        }
#pragma unroll
        for (int jp = 0; jp < 2; jp++) {
            int na = n0 + 2 * jp, nb = na + 1;
            float y0l, y0h, y1l, y1h, h0l, h0h, h1l, h1h;
            unpack2(ya[jp][0], y0l, y0h);
            unpack2(ya[jp][1], y1l, y1h);
            unpack2(ha[jp][0], h0l, h0h);
            unpack2(ha[jp][1], h1l, h1h);
            if (na < N) {
                *(float2*)(d_y + (size_t)na * H_DIM + 2 * lane) = make_float2(y0l, y1l);
                *(float2*)(d_h + (size_t)na * H_DIM + 2 * lane) = make_float2(h0l + bias0, h1l + bias1);
            }
            if (nb < N) {
                *(float2*)(d_y + (size_t)nb * H_DIM + 2 * lane) = make_float2(y0h, y1h);
                *(float2*)(d_h + (size_t)nb * H_DIM + 2 * lane) = make_float2(h0h + bias0, h1h + bias1);
            }
        }
        __syncwarp();
    }
}

// ---------------- k_hist: (dst,rel) counts + per-block rel hist + dst counts
__global__ void k_hist(const int* __restrict__ ei, const int* __restrict__ et,
                       int E, int R, int chunk) {
    __shared__ int h[R_CAP];
    int t = threadIdx.x;
    if (t < R) h[t] = 0;
    __syncthreads();
    int s = blockIdx.x * chunk;
    int e_end = min(E, s + chunk);
    for (int e = s + t; e < e_end; e += blockDim.x) {
        int dst = ei[E + e];
        int r = et[e];
        atomicAdd(&d_cnt[(size_t)dst * R + r], 1);
        atomicAdd(&d_dcnt[dst], 1);
        atomicAdd(&h[r], 1);
    }
    __syncthreads();
    if (t < R) d_bhist[t * NBLK_B + blockIdx.x] = h[t];
}

// ---------------- k_bscan: scan per-block rel histograms --------
__global__ void k_bscan(int R, int E) {
    __shared__ int ssum[1024];
    int t = threadIdx.x;
    int base = t * 8;             // 1024*8 = 8192 = R_CAP*NBLK_B
    int v[8];
    int s = 0;
#pragma unroll
    for (int i = 0; i < 8; i++) { v[i] = s; s += d_bhist[base + i]; }
    ssum[t] = s;
    __syncthreads();
    for (int off = 1; off < 1024; off <<= 1) {
        int add = (t >= off) ? ssum[t - off] : 0;
        __syncthreads();
        ssum[t] += add;
        __syncthreads();
    }
    int excl = ssum[t] - s;
#pragma unroll
    for (int i = 0; i < 8; i++) d_boff[base + i] = excl + v[i];
    if (t < R) {
        int chunks_per_rel = NBLK_B / 8;
        int st = (t == 0) ? 0 : ssum[t * chunks_per_rel - 1];
        int en = ssum[(t + 1) * chunks_per_rel - 1];
        d_bstart[t] = st;
        d_bcnt[t] = en - st;
    }
}

// ---------------- k_scatter: edges -> relation buckets ----------
__global__ void k_scatter(const int* __restrict__ ei, const int* __restrict__ et,
                          int E, int R, int chunk) {
    __shared__ int c[R_CAP];
    int t = threadIdx.x;
    if (t < R) c[t] = d_boff[t * NBLK_B + blockIdx.x];
    __syncthreads();
    int s = blockIdx.x * chunk;
    int e_end = min(E, s + chunk);
    for (int e = s + t; e < e_end; e += blockDim.x) {
        int r = et[e];
        int pos = atomicAdd(&c[r], 1);
        d_bedge[pos] = make_int2(ei[e], ei[E + e]);
    }
}

// ---------------- dst-CSR scan (3 kernels over d_dcnt[N]) ------
__global__ void k_dscan1(int N, int chunk) {
    __shared__ int s[512];
    int b = blockIdx.x, t = threadIdx.x;
    int base = b * chunk;
    int idx = base + t;
    int v = (t < chunk && idx < N) ? d_dcnt[idx] : 0;
    s[t] = v;
    __syncthreads();
    for (int off = 1; off < 512; off <<= 1) {
        int add = (t >= off) ? s[t - off] : 0;
        __syncthreads();
        s[t] += add;
        __syncthreads();
    }
    if (t < chunk && idx < N) d_doff[idx] = s[t] - v;   // local exclusive
    if (t == 511) d_dpartial[b] = s[511];
}
__global__ void k_dscan2(int E, int N) {
    __shared__ int s[DSCAN_B];
    int t = threadIdx.x;
    int v = d_dpartial[t];
    s[t] = v;
    __syncthreads();
    for (int off = 1; off < DSCAN_B; off <<= 1) {
        int add = (t >= off) ? s[t - off] : 0;
        __syncthreads();
        s[t] += add;
        __syncthreads();
    }
    d_dpartial[t] = s[t] - v;    // exclusive base per block
    if (t == 0) d_doff[N] = E;
}
__global__ void k_dscan3(int N, int chunk) {
    int b = blockIdx.x;
    int base = b * chunk;
    int add = d_dpartial[b];
    for (int i = threadIdx.x; i < chunk; i += blockDim.x) {
        int idx = base + i;
        if (idx < N) {
            int o = d_doff[idx] + add;
            d_doff[idx] = o;
            d_dcur[idx] = o;
        }
    }
}

// ---------------- k_dscatter: edges -> dst-sorted (src, nrm) ----
__global__ void k_dscatter(const int* __restrict__ ei, const float* __restrict__ nrm,
                           int E) {
    int t = blockIdx.x * blockDim.x + threadIdx.x;
    int nth = gridDim.x * blockDim.x;
    for (int e = t; e < E; e += nth) {
        int dst = ei[E + e];
        int pos = atomicAdd(&d_dcur[dst], 1);
        d_dedge[pos] = make_int2(ei[e], __float_as_int(nrm[e]));
    }
}

// ---------------- k_agg1b: warp per dst, NO atomics -------------
// h[dst] += sum_e y[src_e] * nrm_e
__global__ void k_agg1b(int N) {
    int lane = threadIdx.x & 31;
    int d = (blockIdx.x * blockDim.x + threadIdx.x) >> 5;
    if (d >= N) return;
    int s = d_doff[d], e2 = d_doff[d + 1];
    float* hp = d_h + (size_t)d * H_DIM + 2 * lane;
    float2 acc = *(float2*)hp;
    int i = s;
    for (; i + 2 <= e2; i += 2) {
        int2 a = d_dedge[i];
        int2 b = d_dedge[i + 1];
        float2 y0 = *(const float2*)(d_y + (size_t)a.x * H_DIM + 2 * lane);
        float2 y1 = *(const float2*)(d_y + (size_t)b.x * H_DIM + 2 * lane);
        float w0 = __int_as_float(a.y), w1 = __int_as_float(b.y);
        acc.x += y0.x * w0; acc.y += y0.y * w0;
        acc.x += y1.x * w1; acc.y += y1.y * w1;
    }
    if (i < e2) {
        int2 a = d_dedge[i];
        float2 y0 = *(const float2*)(d_y + (size_t)a.x * H_DIM + 2 * lane);
        float w0 = __int_as_float(a.y);
        acc.x += y0.x * w0; acc.y += y0.y * w0;
    }
    *(float2*)hp = acc;
}

// ---------------- k_oroot: o = h @ w2_root + b2 (FFMA2) ---------
__global__ void k_oroot(const float* __restrict__ w2, const float* __restrict__ b2, int N) {
    __shared__ float sw[4096];
    __shared__ u64 sp2[8][128];
    for (int i = threadIdx.x; i < 4096; i += blockDim.x) sw[i] = w2[i];
    __syncthreads();
    int lane = threadIdx.x & 31;
    int wl   = threadIdx.x >> 5;
    int warp = (blockIdx.x * blockDim.x + threadIdx.x) >> 5;
    int nw   = (gridDim.x * blockDim.x) >> 5;
    float bias0 = b2[2 * lane], bias1 = b2[2 * lane + 1];
    int nquad = (N + 3) >> 2;
    for (int q = warp; q < nquad; q += nw) {
        int n0 = 4 * q;
#pragma unroll
        for (int jp = 0; jp < 2; jp++) {
            int na = n0 + 2 * jp, nb = na + 1;
#pragma unroll
            for (int h2 = 0; h2 < 2; h2++) {
                int k = h2 * 32 + lane;
                float f0 = (na < N) ? d_h[(size_t)na * H_DIM + k] : 0.f;
                float f1 = (nb < N) ? d_h[(size_t)nb * H_DIM + k] : 0.f;
                sp2[wl][jp * 64 + k] = pack2(f0, f1);
            }
        }
        __syncwarp();
        u64 a[2][2] = {{0, 0}, {0, 0}};
#pragma unroll 8
        for (int k = 0; k < H_DIM; k++) {
            float2 w = *(const float2*)(sw + k * 64 + 2 * lane);
            u64 xp0 = sp2[wl][k];
            u64 xp1 = sp2[wl][64 + k];
            u64 Wx = splat2(w.x), Wy = splat2(w.y);
            ffma2(a[0][0], xp0, Wx); ffma2(a[0][1], xp0, Wy);
            ffma2(a[1][0], xp1, Wx); ffma2(a[1][1], xp1, Wy);
        }
#pragma unroll
        for (int jp = 0; jp < 2; jp++) {
            int na = n0 + 2 * jp, nb = na + 1;
            float a0l, a0h, a1l, a1h;
            unpack2(a[jp][0], a0l, a0h);
            unpack2(a[jp][1], a1l, a1h);
            if (na < N)
                *(float2*)(d_o + (size_t)na * H_DIM + 2 * lane) =
                    make_float2(a0l + bias0, a1l + bias1);
            if (nb < N)
                *(float2*)(d_o + (size_t)nb * H_DIM + 2 * lane) =
                    make_float2(a0h + bias0, a1h + bias1);
        }
        __syncwarp();
    }
}

// ---------------- k_rgcn2: bucketed, W in smem, 4 edges/warp ----
__global__ void k_rgcn2(int R) {
    __shared__ float sW[4096];
    __shared__ u64 shp[8][128];
    int rel = blockIdx.x % R;
    int chunk = blockIdx.x / R;
    int nchunk = gridDim.x / R;
    const float* __restrict__ W = d_W + (size_t)rel * 4096;
    for (int i = threadIdx.x; i < 1024; i += blockDim.x)
        *(float4*)(sW + 4 * i) = *(const float4*)(W + 4 * i);
    __syncthreads();
    int start = d_bstart[rel], cnt = d_bcnt[rel];
    int lane = threadIdx.x & 31, wl = threadIdx.x >> 5;
    int ngroups = (cnt + 3) >> 2;
    int wstride = nchunk * 8;
    for (int g = chunk * 8 + wl; g < ngroups; g += wstride) {
        int base = start + g * 4;
        int m = min(4, cnt - g * 4);
        int2 ev = make_int2(0, 0);
        if (lane < m) ev = d_bedge[base + lane];
#pragma unroll
        for (int jp = 0; jp < 2; jp++) {
            int s0 = __shfl_sync(0xffffffffu, ev.x, 2 * jp);
            int s1 = __shfl_sync(0xffffffffu, ev.x, 2 * jp + 1);
#pragma unroll
            for (int h2 = 0; h2 < 2; h2++) {
                int k = h2 * 32 + lane;
                float f0 = d_h[(size_t)s0 * H_DIM + k];
                float f1 = d_h[(size_t)s1 * H_DIM + k];
                shp[wl][jp * 64 + k] = pack2(f0, f1);
            }
        }
        __syncwarp();
        u64 a[2][2] = {{0, 0}, {0, 0}};
#pragma unroll 8
        for (int k = 0; k < H_DIM; k++) {
            float2 w = *(const float2*)(&sW[k * 64 + 2 * lane]);
            u64 xp0 = shp[wl][k];
            u64 xp1 = shp[wl][64 + k];
            u64 Wx = splat2(w.x), Wy = splat2(w.y);
            ffma2(a[0][0], xp0, Wx); ffma2(a[0][1], xp0, Wy);
            ffma2(a[1][0], xp1, Wx); ffma2(a[1][1], xp1, Wy);
        }
#pragma unroll
        for (int jp = 0; jp < 2; jp++) {
            float a0l, a0h, a1l, a1h;
            unpack2(a[jp][0], a0l, a0h);
            unpack2(a[jp][1], a1l, a1h);
            int j0 = 2 * jp, j1 = 2 * jp + 1;
            if (j0 < m) {
                int dj = __shfl_sync(0xffffffffu, ev.y, j0);
                int c = d_cnt[(size_t)dj * R + rel];
                float inv = 1.f / (float)(c > 1 ? c : 1);
                red_add_v2(d_o + (size_t)dj * H_DIM + 2 * lane, a0l * inv, a1l * inv);
            }
            if (j1 < m) {
                int dj = __shfl_sync(0xffffffffu, ev.y, j1);
                int c = d_cnt[(size_t)dj * R + rel];
                float inv = 1.f / (float)(c > 1 ? c : 1);
                red_add_v2(d_o + (size_t)dj * H_DIM + 2 * lane, a0h * inv, a1h * inv);
            }
        }
        __syncwarp();
    }
}

// ---------------- k_pool_x: per-graph sum+max over x dims -------
__global__ void k_pool_x(const float* __restrict__ x, int G) {
    int g = blockIdx.x;
    int s = d_offs[g], e = d_offs[g + 1];
    int d = threadIdx.x;                 // 128 threads
    float sum = 0.f, mx = -INFINITY;
#pragma unroll 4
    for (int n = s; n < e; n++) {
        float v = x[(size_t)n * F_DIM + d];
        sum += v; mx = fmaxf(mx, v);
    }
    d_pool[(size_t)g * P_DIM + d] = sum;
    d_pool[(size_t)g * P_DIM + 192 + d] = mx;
}

// ---------------- k_pool_o: per-graph sum+max over o dims -------
__global__ void k_pool_o(int G) {
    int g = blockIdx.x;
    int s = d_offs[g], e = d_offs[g + 1];
    int t = threadIdx.x;                 // 64 threads
    float sum = 0.f, mx = -INFINITY;
#pragma unroll 4
    for (int n = s; n < e; n++) {
        float v = d_o[(size_t)n * H_DIM + t];
        sum += v; mx = fmaxf(mx, v);
    }
    d_pool[(size_t)g * P_DIM + 128 + t] = sum;
    d_pool[(size_t)g * P_DIM + 320 + t] = mx;
}

// ---------------- k_head: linear->relu->linear->log_softmax -----
__global__ void k_head(const float* __restrict__ lin_w, const float* __restrict__ lin_b,
                       const float* __restrict__ fc_w, const float* __restrict__ fc_b,
                       float* __restrict__ out, int G) {
    __shared__ float sp[P_DIM];
    __shared__ float hid[H_DIM];
    __shared__ float lg[C_DIM];
    __shared__ float lse;
    int g = blockIdx.x, t = threadIdx.x;   // 64 threads
    for (int i = t; i < P_DIM; i += 64) sp[i] = d_pool[(size_t)g * P_DIM + i];
    __syncthreads();
    float acc = lin_b[t];
#pragma unroll 8
    for (int k = 0; k < P_DIM; k++) acc += sp[k] * lin_w[k * H_DIM + t];
    hid[t] = fmaxf(acc, 0.f);
    __syncthreads();
    if (t < C_DIM) {
        float a = fc_b[t];
#pragma unroll
        for (int k = 0; k < H_DIM; k++) a += hid[k] * fc_w[k * C_DIM + t];
        lg[t] = a;
    }
    __syncthreads();
    if (t == 0) {
        float m = -INFINITY;
        for (int j = 0; j < C_DIM; j++) m = fmaxf(m, lg[j]);
        float s2 = 0.f;
        for (int j = 0; j < C_DIM; j++) s2 += expf(lg[j] - m);
        lse = m + logf(s2);
    }
    __syncthreads();
    if (t < C_DIM) out[(size_t)g * C_DIM + t] = lg[t] - lse;
}

// ---------------- launch ----------------------------------------
extern "C" void kernel_launch(void* const* d_in, const int* in_sizes, int n_in,
                              void* d_out, int out_size) {
    int o = (n_in >= 17) ? 0 : -1;
    const float* x       = (const float*)d_in[0];
    const int*   ei      = (const int*)d_in[1];
    const float* enorm   = (const float*)d_in[2];
    const int*   etype   = (const int*)d_in[3];
    const int*   seql    = (const int*)d_in[4];
    const float* w1_rel  = (const float*)d_in[6 + o];
    const float* w1_root = (const float*)d_in[7 + o];
    const float* b1      = (const float*)d_in[8 + o];
    const float* bases   = (const float*)d_in[9 + o];
    const float* comp    = (const float*)d_in[10 + o];
    const float* w2      = (const float*)d_in[11 + o];
    const float* b2      = (const float*)d_in[12 + o];
    const float* lin_w   = (const float*)d_in[13 + o];
    const float* lin_b   = (const float*)d_in[14 + o];
    const float* fc_w    = (const float*)d_in[15 + o];
    const float* fc_b    = (const float*)d_in[16 + o];

    int N  = in_sizes[0] / F_DIM;
    int E  = in_sizes[2];
    int G  = in_sizes[4];
    int NB = in_sizes[9 + o] / (H_DIM * H_DIM);
    int R  = in_sizes[10 + o] / NB;
    float* out = (float*)d_out;
    (void)out_size;

    // Side streams + events created once (first call happens OUTSIDE graph
    // capture — the harness does a correctness run first). Handles are
    // stateless w.r.t. work: every call enqueues the identical kernel DAG.
    static cudaStream_t sA = 0, sB = 0;
    static cudaEvent_t evRoot = 0, evA = 0, evB = 0;
    if (sA == 0) {
        cudaStreamCreateWithFlags(&sA, cudaStreamNonBlocking);
        cudaStreamCreateWithFlags(&sB, cudaStreamNonBlocking);
        cudaEventCreateWithFlags(&evRoot, cudaEventDisableTiming);
        cudaEventCreateWithFlags(&evA, cudaEventDisableTiming);
        cudaEventCreateWithFlags(&evB, cudaEventDisableTiming);
        cudaFuncSetAttribute(k_proj, cudaFuncAttributeMaxDynamicSharedMemorySize, 81920);
    }

    int chunk  = (E + NBLK_B - 1) / NBLK_B;
    int dchunk = (N + DSCAN_B - 1) / DSCAN_B;   // <= 512 for N<=131072

    // fork
    cudaEventRecord(evRoot, 0);
    cudaStreamWaitEvent(sA, evRoot, 0);
    cudaStreamWaitEvent(sB, evRoot, 0);

    // stream A: all edge bucketing (independent of proj)
    k_prep<<<2048, 256, 0, sA>>>(comp, bases, R, NB, N);
    k_hist<<<NBLK_B, 256, 0, sA>>>(ei, etype, E, R, chunk);
    k_bscan<<<1, 1024, 0, sA>>>(R, E);
    k_scatter<<<NBLK_B, 256, 0, sA>>>(ei, etype, E, R, chunk);
    k_dscan1<<<DSCAN_B, 512, 0, sA>>>(N, dchunk);
    k_dscan2<<<1, DSCAN_B, 0, sA>>>(E, N);
    k_dscan3<<<DSCAN_B, 256, 0, sA>>>(N, dchunk);
    k_dscatter<<<512, 256, 0, sA>>>(ei, enorm, E);
    cudaEventRecord(evA, sA);

    // stream B: graph offsets + x-half of pooling (independent of everything)
    k_scan<<<1, 1024, 0, sB>>>(seql, G);
    k_pool_x<<<G, 128, 0, sB>>>(x, G);
    cudaEventRecord(evB, sB);

    // main stream: critical path
    k_proj<<<444, 256, 81920>>>(x, w1_rel, w1_root, b1, N);
    cudaStreamWaitEvent(0, evA, 0);
    k_agg1b<<<(N + 7) / 8, 256>>>(N);
    k_oroot<<<592, 256>>>(w2, b2, N);
    k_rgcn2<<<R * 64, 256>>>(R);
    k_pool_o<<<G, 64>>>(G);
    cudaStreamWaitEvent(0, evB, 0);
    k_head<<<G, 64>>>(lin_w, lin_b, fc_w, fc_b, out, G);
}

// round 9
// speedup vs baseline: 1.9551x; 1.1388x over previous
#include <cuda_runtime.h>
#include <cuda_bf16.h>
#include <math.h>

// ---------------- compile-time architecture dims ----------------
#define F_DIM 128
#define H_DIM 64
#define C_DIM 10
#define P_DIM 384           // 2*(F+H)
#define N_CAP 100000
#define R_CAP 16
#define G_CAP 1024
#define E_CAP 1000000
#define NBLK_B 512          // blocks for hist/scatter passes
#define DSCAN_B 256         // blocks for dst scan

// ---------------- scratch (static device arrays; no allocs) -----
__device__ float d_W[R_CAP * H_DIM * H_DIM];   // 256 KB  [r][k][n]
__device__ float d_y[(size_t)N_CAP * H_DIM];   // 25.6 MB  x @ w1_rel
__device__ float d_h[(size_t)N_CAP * H_DIM];   // 25.6 MB  node hidden
__device__ float d_o[(size_t)N_CAP * H_DIM];   // 25.6 MB  rgcn out
__device__ int   d_cnt[(size_t)N_CAP * R_CAP]; // 6.4 MB   per (node, rel) counts
__device__ float d_pool[(size_t)G_CAP * P_DIM];
__device__ int   d_offs[G_CAP + 1];
// relation bucketing (for k_rgcn3)
__device__ int2  d_bedge[E_CAP];               // (src, dst) sorted by relation
__device__ int   d_bhist[R_CAP * NBLK_B];
__device__ int   d_boff [R_CAP * NBLK_B];
__device__ int   d_bstart[R_CAP];
__device__ int   d_bcnt  [R_CAP];
// dst bucketing (for k_agg1b, atomic-free aggregation)
__device__ int2  d_dedge[E_CAP];               // (src, nrm_bits) sorted by dst
__device__ int   d_dcnt[N_CAP];
__device__ int   d_doff[N_CAP + 1];
__device__ int   d_dcur[N_CAP];
__device__ int   d_dpartial[DSCAN_B];

// ---------------- vector reductions (sm_90+) --------------------
__device__ __forceinline__ void red_add_v2(float* addr, float a, float b) {
    asm volatile("red.global.add.v2.f32 [%0], {%1, %2};"
                 :: "l"(addr), "f"(a), "f"(b) : "memory");
}

// ---------------- packed f32x2 helpers (sm_103a FFMA2) ----------
typedef unsigned long long u64;
__device__ __forceinline__ void ffma2(u64& acc, u64 a, u64 b) {
    asm("fma.rn.f32x2 %0, %1, %2, %0;" : "+l"(acc) : "l"(a), "l"(b));
}
__device__ __forceinline__ u64 pack2(float lo, float hi) {
    u64 r;
    asm("mov.b64 %0, {%1, %2};" : "=l"(r) : "f"(lo), "f"(hi));
    return r;
}
__device__ __forceinline__ u64 splat2(float w) {
    u64 r;
    asm("mov.b64 %0, {%1, %1};" : "=l"(r) : "f"(w));
    return r;
}
__device__ __forceinline__ void unpack2(u64 v, float& lo, float& hi) {
    asm("mov.b64 {%0, %1}, %2;" : "=f"(lo), "=f"(hi) : "l"(v));
}

// ---------------- tf32 mma helpers ------------------------------
__device__ __forceinline__ unsigned f2tf32(float x) {
    unsigned r;
    asm("cvt.rna.tf32.f32 %0, %1;" : "=r"(r) : "f"(x));
    return r;
}
__device__ __forceinline__ void mma_tf32(float& c0, float& c1, float& c2, float& c3,
                                         unsigned a0, unsigned a1, unsigned a2, unsigned a3,
                                         unsigned b0, unsigned b1) {
    asm volatile("mma.sync.aligned.m16n8k8.row.col.f32.tf32.tf32.f32 "
                 "{%0,%1,%2,%3}, {%4,%5,%6,%7}, {%8,%9}, {%0,%1,%2,%3};"
                 : "+f"(c0), "+f"(c1), "+f"(c2), "+f"(c3)
                 : "r"(a0), "r"(a1), "r"(a2), "r"(a3), "r"(b0), "r"(b1));
}

// ---------------- k_prep: zero counts, W = comp @ bases ----------
__global__ void k_prep(const float* __restrict__ comp, const float* __restrict__ bases,
                       int R, int NB, int N) {
    int tid = blockIdx.x * blockDim.x + threadIdx.x;
    int nth = gridDim.x * blockDim.x;
    int total_cnt = N * R;
    for (int i = tid; i < total_cnt; i += nth) d_cnt[i] = 0;
    for (int i = tid; i < N; i += nth) d_dcnt[i] = 0;
    int wtot = R * H_DIM * H_DIM;
    for (int i = tid; i < wtot; i += nth) {
        int r = i >> 12;          // / 4096
        int ij = i & 4095;
        float acc = 0.f;
        for (int b = 0; b < NB; b++)
            acc += comp[r * NB + b] * bases[b * 4096 + ij];
        d_W[i] = acc;
    }
}

// ---------------- k_scan: exclusive prefix of seq_lengths -------
__global__ void k_scan(const int* __restrict__ sl, int G) {
    __shared__ int s[1024];
    int t = threadIdx.x;
    s[t] = (t < G) ? sl[t] : 0;
    __syncthreads();
    for (int off = 1; off < 1024; off <<= 1) {
        int add = (t >= off) ? s[t - off] : 0;
        __syncthreads();
        s[t] += add;
        __syncthreads();
    }
    if (t == 0) d_offs[0] = 0;
    if (t < G) d_offs[t + 1] = s[t];
}

// ---------------- k_proj: y = x@w1_rel ; h = x@w1_root + b1 -----
__global__ void k_proj(const float* __restrict__ x, const float* __restrict__ w_rel,
                       const float* __restrict__ w_root, const float* __restrict__ b1,
                       int N) {
    extern __shared__ float sw[];
    u64* spair = (u64*)(sw + 16384);
    for (int i = threadIdx.x; i < 8192; i += blockDim.x) {
        sw[i] = w_rel[i];
        sw[8192 + i] = w_root[i];
    }
    __syncthreads();
    int lane = threadIdx.x & 31;
    int wl   = threadIdx.x >> 5;
    int warp = (blockIdx.x * blockDim.x + threadIdx.x) >> 5;
    int nw   = (gridDim.x * blockDim.x) >> 5;
    u64* sx = spair + wl * 256;       // [jp*128 + k]
    float bias0 = b1[2 * lane], bias1 = b1[2 * lane + 1];
    int nquad = (N + 3) >> 2;
    for (int q = warp; q < nquad; q += nw) {
        int n0 = 4 * q;
#pragma unroll
        for (int jp = 0; jp < 2; jp++) {
            int na = n0 + 2 * jp, nb = na + 1;
#pragma unroll
            for (int kb = 0; kb < 4; kb++) {
                int k = kb * 32 + lane;
                float f0 = (na < N) ? x[(size_t)na * F_DIM + k] : 0.f;
                float f1 = (nb < N) ? x[(size_t)nb * F_DIM + k] : 0.f;
                sx[jp * 128 + k] = pack2(f0, f1);
            }
        }
        __syncwarp();
        u64 ya[2][2] = {{0, 0}, {0, 0}};
        u64 ha[2][2] = {{0, 0}, {0, 0}};
#pragma unroll 8
        for (int k = 0; k < F_DIM; k++) {
            float2 wr = *(const float2*)(sw + k * 64 + 2 * lane);
            float2 wo = *(const float2*)(sw + 8192 + k * 64 + 2 * lane);
            u64 xp0 = sx[k];
            u64 xp1 = sx[128 + k];
            u64 Wrx = splat2(wr.x), Wry = splat2(wr.y);
            u64 Wox = splat2(wo.x), Woy = splat2(wo.y);
            ffma2(ya[0][0], xp0, Wrx); ffma2(ya[0][1], xp0, Wry);
            ffma2(ha[0][0], xp0, Wox); ffma2(ha[0][1], xp0, Woy);
            ffma2(ya[1][0], xp1, Wrx); ffma2(ya[1][1], xp1, Wry);
            ffma2(ha[1][0], xp1, Wox); ffma2(ha[1][1], xp1, Woy);
        }
#pragma unroll
        for (int jp = 0; jp < 2; jp++) {
            int na = n0 + 2 * jp, nb = na + 1;
            float y0l, y0h, y1l, y1h, h0l, h0h, h1l, h1h;
            unpack2(ya[jp][0], y0l, y0h);
            unpack2(ya[jp][1], y1l, y1h);
            unpack2(ha[jp][0], h0l, h0h);
            unpack2(ha[jp][1], h1l, h1h);
            if (na < N) {
                *(float2*)(d_y + (size_t)na * H_DIM + 2 * lane) = make_float2(y0l, y1l);
                *(float2*)(d_h + (size_t)na * H_DIM + 2 * lane) = make_float2(h0l + bias0, h1l + bias1);
            }
            if (nb < N) {
                *(float2*)(d_y + (size_t)nb * H_DIM + 2 * lane) = make_float2(y0h, y1h);
                *(float2*)(d_h + (size_t)nb * H_DIM + 2 * lane) = make_float2(h0h + bias0, h1h + bias1);
            }
        }
        __syncwarp();
    }
}

// ---------------- k_hist: (dst,rel) counts + per-block rel hist + dst counts
__global__ void k_hist(const int* __restrict__ ei, const int* __restrict__ et,
                       int E, int R, int chunk) {
    __shared__ int h[R_CAP];
    int t = threadIdx.x;
    if (t < R) h[t] = 0;
    __syncthreads();
    int s = blockIdx.x * chunk;
    int e_end = min(E, s + chunk);
    for (int e = s + t; e < e_end; e += blockDim.x) {
        int dst = ei[E + e];
        int r = et[e];
        atomicAdd(&d_cnt[(size_t)dst * R + r], 1);
        atomicAdd(&d_dcnt[dst], 1);
        atomicAdd(&h[r], 1);
    }
    __syncthreads();
    if (t < R) d_bhist[t * NBLK_B + blockIdx.x] = h[t];
}

// ---------------- k_bscan: scan per-block rel histograms --------
__global__ void k_bscan(int R, int E) {
    __shared__ int ssum[1024];
    int t = threadIdx.x;
    int base = t * 8;             // 1024*8 = 8192 = R_CAP*NBLK_B
    int v[8];
    int s = 0;
#pragma unroll
    for (int i = 0; i < 8; i++) { v[i] = s; s += d_bhist[base + i]; }
    ssum[t] = s;
    __syncthreads();
    for (int off = 1; off < 1024; off <<= 1) {
        int add = (t >= off) ? ssum[t - off] : 0;
        __syncthreads();
        ssum[t] += add;
        __syncthreads();
    }
    int excl = ssum[t] - s;
#pragma unroll
    for (int i = 0; i < 8; i++) d_boff[base + i] = excl + v[i];
    if (t < R) {
        int chunks_per_rel = NBLK_B / 8;
        int st = (t == 0) ? 0 : ssum[t * chunks_per_rel - 1];
        int en = ssum[(t + 1) * chunks_per_rel - 1];
        d_bstart[t] = st;
        d_bcnt[t] = en - st;
    }
}

// ---------------- k_scatter: edges -> relation buckets ----------
__global__ void k_scatter(const int* __restrict__ ei, const int* __restrict__ et,
                          int E, int R, int chunk) {
    __shared__ int c[R_CAP];
    int t = threadIdx.x;
    if (t < R) c[t] = d_boff[t * NBLK_B + blockIdx.x];
    __syncthreads();
    int s = blockIdx.x * chunk;
    int e_end = min(E, s + chunk);
    for (int e = s + t; e < e_end; e += blockDim.x) {
        int r = et[e];
        int pos = atomicAdd(&c[r], 1);
        d_bedge[pos] = make_int2(ei[e], ei[E + e]);
    }
}

// ---------------- dst-CSR scan (3 kernels over d_dcnt[N]) ------
__global__ void k_dscan1(int N, int chunk) {
    __shared__ int s[512];
    int b = blockIdx.x, t = threadIdx.x;
    int base = b * chunk;
    int idx = base + t;
    int v = (t < chunk && idx < N) ? d_dcnt[idx] : 0;
    s[t] = v;
    __syncthreads();
    for (int off = 1; off < 512; off <<= 1) {
        int add = (t >= off) ? s[t - off] : 0;
        __syncthreads();
        s[t] += add;
        __syncthreads();
    }
    if (t < chunk && idx < N) d_doff[idx] = s[t] - v;   // local exclusive
    if (t == 511) d_dpartial[b] = s[511];
}
__global__ void k_dscan2(int E, int N) {
    __shared__ int s[DSCAN_B];
    int t = threadIdx.x;
    int v = d_dpartial[t];
    s[t] = v;
    __syncthreads();
    for (int off = 1; off < DSCAN_B; off <<= 1) {
        int add = (t >= off) ? s[t - off] : 0;
        __syncthreads();
        s[t] += add;
        __syncthreads();
    }
    d_dpartial[t] = s[t] - v;    // exclusive base per block
    if (t == 0) d_doff[N] = E;
}
__global__ void k_dscan3(int N, int chunk) {
    int b = blockIdx.x;
    int base = b * chunk;
    int add = d_dpartial[b];
    for (int i = threadIdx.x; i < chunk; i += blockDim.x) {
        int idx = base + i;
        if (idx < N) {
            int o = d_doff[idx] + add;
            d_doff[idx] = o;
            d_dcur[idx] = o;
        }
    }
}

// ---------------- k_dscatter: edges -> dst-sorted (src, nrm) ----
__global__ void k_dscatter(const int* __restrict__ ei, const float* __restrict__ nrm,
                           int E) {
    int t = blockIdx.x * blockDim.x + threadIdx.x;
    int nth = gridDim.x * blockDim.x;
    for (int e = t; e < E; e += nth) {
        int dst = ei[E + e];
        int pos = atomicAdd(&d_dcur[dst], 1);
        d_dedge[pos] = make_int2(ei[e], __float_as_int(nrm[e]));
    }
}

// ---------------- k_agg1b: warp per dst, NO atomics -------------
__global__ void k_agg1b(int N) {
    int lane = threadIdx.x & 31;
    int d = (blockIdx.x * blockDim.x + threadIdx.x) >> 5;
    if (d >= N) return;
    int s = d_doff[d], e2 = d_doff[d + 1];
    float* hp = d_h + (size_t)d * H_DIM + 2 * lane;
    float2 acc = *(float2*)hp;
    int i = s;
    for (; i + 2 <= e2; i += 2) {
        int2 a = d_dedge[i];
        int2 b = d_dedge[i + 1];
        float2 y0 = *(const float2*)(d_y + (size_t)a.x * H_DIM + 2 * lane);
        float2 y1 = *(const float2*)(d_y + (size_t)b.x * H_DIM + 2 * lane);
        float w0 = __int_as_float(a.y), w1 = __int_as_float(b.y);
        acc.x += y0.x * w0; acc.y += y0.y * w0;
        acc.x += y1.x * w1; acc.y += y1.y * w1;
    }
    if (i < e2) {
        int2 a = d_dedge[i];
        float2 y0 = *(const float2*)(d_y + (size_t)a.x * H_DIM + 2 * lane);
        float w0 = __int_as_float(a.y);
        acc.x += y0.x * w0; acc.y += y0.y * w0;
    }
    *(float2*)hp = acc;
}

// ---------------- k_oroot: o = h @ w2_root + b2 (FFMA2) ---------
__global__ void k_oroot(const float* __restrict__ w2, const float* __restrict__ b2, int N) {
    __shared__ float sw[4096];
    __shared__ u64 sp2[8][128];
    for (int i = threadIdx.x; i < 4096; i += blockDim.x) sw[i] = w2[i];
    __syncthreads();
    int lane = threadIdx.x & 31;
    int wl   = threadIdx.x >> 5;
    int warp = (blockIdx.x * blockDim.x + threadIdx.x) >> 5;
    int nw   = (gridDim.x * blockDim.x) >> 5;
    float bias0 = b2[2 * lane], bias1 = b2[2 * lane + 1];
    int nquad = (N + 3) >> 2;
    for (int q = warp; q < nquad; q += nw) {
        int n0 = 4 * q;
#pragma unroll
        for (int jp = 0; jp < 2; jp++) {
            int na = n0 + 2 * jp, nb = na + 1;
#pragma unroll
            for (int h2 = 0; h2 < 2; h2++) {
                int k = h2 * 32 + lane;
                float f0 = (na < N) ? d_h[(size_t)na * H_DIM + k] : 0.f;
                float f1 = (nb < N) ? d_h[(size_t)nb * H_DIM + k] : 0.f;
                sp2[wl][jp * 64 + k] = pack2(f0, f1);
            }
        }
        __syncwarp();
        u64 a[2][2] = {{0, 0}, {0, 0}};
#pragma unroll 8
        for (int k = 0; k < H_DIM; k++) {
            float2 w = *(const float2*)(sw + k * 64 + 2 * lane);
            u64 xp0 = sp2[wl][k];
            u64 xp1 = sp2[wl][64 + k];
            u64 Wx = splat2(w.x), Wy = splat2(w.y);
            ffma2(a[0][0], xp0, Wx); ffma2(a[0][1], xp0, Wy);
            ffma2(a[1][0], xp1, Wx); ffma2(a[1][1], xp1, Wy);
        }
#pragma unroll
        for (int jp = 0; jp < 2; jp++) {
            int na = n0 + 2 * jp, nb = na + 1;
            float a0l, a0h, a1l, a1h;
            unpack2(a[jp][0], a0l, a0h);
            unpack2(a[jp][1], a1l, a1h);
            if (na < N)
                *(float2*)(d_o + (size_t)na * H_DIM + 2 * lane) =
                    make_float2(a0l + bias0, a1l + bias1);
            if (nb < N)
                *(float2*)(d_o + (size_t)nb * H_DIM + 2 * lane) =
                    make_float2(a0h + bias0, a1h + bias1);
        }
        __syncwarp();
    }
}

// ---------------- k_rgcn3: bucketed tf32 MMA, 16 edges/warp -----
// o[dst] += (h[src] @ W[rel]) / cnt[dst,rel]   via m16n8k8 tf32 split
__global__ __launch_bounds__(256) void k_rgcn3(int R) {
    __shared__ unsigned sWhi[64 * 68];     // W^T [n][k], stride 68 (bank-safe)
    __shared__ unsigned sWlo[64 * 68];
    int rel = blockIdx.x % R;
    int chunk = blockIdx.x / R;
    int nchunk = gridDim.x / R;
    const float* __restrict__ W = d_W + (size_t)rel * 4096;
    for (int i = threadIdx.x; i < 4096; i += 256) {
        int k = i >> 6, n = i & 63;
        float v = W[i];
        unsigned hi = f2tf32(v);
        float lo = v - __uint_as_float(hi);
        sWhi[n * 68 + k] = hi;
        sWlo[n * 68 + k] = f2tf32(lo);
    }
    __syncthreads();
    int start = d_bstart[rel], cnt = d_bcnt[rel];
    int lane = threadIdx.x & 31, wl = threadIdx.x >> 5;
    int gID = lane >> 2, tig = lane & 3;   // mma group / thread-in-group
    int ngroups = (cnt + 15) >> 4;
    int wstride = nchunk * 8;
    for (int g = chunk * 8 + wl; g < ngroups; g += wstride) {
        int base = start + g * 16;
        int m = min(16, cnt - g * 16);
        int2 ev = make_int2(0, 0);
        float invv = 0.f;
        if (lane < 16) {
            ev = d_bedge[base + min(lane, m - 1)];
            int c = d_cnt[(size_t)ev.y * R + rel];
            invv = 1.f / (float)(c > 1 ? c : 1);
        }
        int s_lo  = __shfl_sync(0xffffffffu, ev.x, gID);
        int s_hi  = __shfl_sync(0xffffffffu, ev.x, gID + 8);
        int d_lo  = __shfl_sync(0xffffffffu, ev.y, gID);
        int d_hi  = __shfl_sync(0xffffffffu, ev.y, gID + 8);
        float ilo = __shfl_sync(0xffffffffu, invv, gID);
        float ihi = __shfl_sync(0xffffffffu, invv, gID + 8);
        // A fragments (row-major 16x64, 8 k-tiles), hi/lo tf32 split
        unsigned Ah[8][4], Al[8][4];
        const float* rl = d_h + (size_t)s_lo * H_DIM;
        const float* rh = d_h + (size_t)s_hi * H_DIM;
#pragma unroll
        for (int kt = 0; kt < 8; kt++) {
            float f0 = rl[kt * 8 + tig];
            float f1 = rh[kt * 8 + tig];
            float f2 = rl[kt * 8 + tig + 4];
            float f3 = rh[kt * 8 + tig + 4];
            Ah[kt][0] = f2tf32(f0); Al[kt][0] = f2tf32(f0 - __uint_as_float(Ah[kt][0]));
            Ah[kt][1] = f2tf32(f1); Al[kt][1] = f2tf32(f1 - __uint_as_float(Ah[kt][1]));
            Ah[kt][2] = f2tf32(f2); Al[kt][2] = f2tf32(f2 - __uint_as_float(Ah[kt][2]));
            Ah[kt][3] = f2tf32(f3); Al[kt][3] = f2tf32(f3 - __uint_as_float(Ah[kt][3]));
        }
#pragma unroll
        for (int nt = 0; nt < 8; nt++) {
            float c0 = 0.f, c1 = 0.f, c2 = 0.f, c3 = 0.f;
            const unsigned* bh = sWhi + (nt * 8 + gID) * 68;
            const unsigned* bl = sWlo + (nt * 8 + gID) * 68;
#pragma unroll
            for (int kt = 0; kt < 8; kt++) {
                unsigned b0h = bh[kt * 8 + tig];
                unsigned b1h = bh[kt * 8 + tig + 4];
                unsigned b0l = bl[kt * 8 + tig];
                unsigned b1l = bl[kt * 8 + tig + 4];
                mma_tf32(c0, c1, c2, c3, Ah[kt][0], Ah[kt][1], Ah[kt][2], Ah[kt][3], b0h, b1h);
                mma_tf32(c0, c1, c2, c3, Ah[kt][0], Ah[kt][1], Ah[kt][2], Ah[kt][3], b0l, b1l);
                mma_tf32(c0, c1, c2, c3, Al[kt][0], Al[kt][1], Al[kt][2], Al[kt][3], b0h, b1h);
            }
            int colg = nt * 8 + 2 * tig;
            if (gID < m)
                red_add_v2(d_o + (size_t)d_lo * H_DIM + colg, c0 * ilo, c1 * ilo);
            if (gID + 8 < m)
                red_add_v2(d_o + (size_t)d_hi * H_DIM + colg, c2 * ihi, c3 * ihi);
        }
    }
}

// ---------------- k_pool_x: per-graph sum+max over x dims -------
__global__ void k_pool_x(const float* __restrict__ x, int G) {
    int g = blockIdx.x;
    int s = d_offs[g], e = d_offs[g + 1];
    int d = threadIdx.x;                 // 128 threads
    float sum = 0.f, mx = -INFINITY;
#pragma unroll 4
    for (int n = s; n < e; n++) {
        float v = x[(size_t)n * F_DIM + d];
        sum += v; mx = fmaxf(mx, v);
    }
    d_pool[(size_t)g * P_DIM + d] = sum;
    d_pool[(size_t)g * P_DIM + 192 + d] = mx;
}

// ---------------- k_pool_o: per-graph sum+max over o dims -------
__global__ void k_pool_o(int G) {
    int g = blockIdx.x;
    int s = d_offs[g], e = d_offs[g + 1];
    int t = threadIdx.x;                 // 64 threads
    float sum = 0.f, mx = -INFINITY;
#pragma unroll 4
    for (int n = s; n < e; n++) {
        float v = d_o[(size_t)n * H_DIM + t];
        sum += v; mx = fmaxf(mx, v);
    }
    d_pool[(size_t)g * P_DIM + 128 + t] = sum;
    d_pool[(size_t)g * P_DIM + 320 + t] = mx;
}

// ---------------- k_head: linear->relu->linear->log_softmax -----
__global__ void k_head(const float* __restrict__ lin_w, const float* __restrict__ lin_b,
                       const float* __restrict__ fc_w, const float* __restrict__ fc_b,
                       float* __restrict__ out, int G) {
    __shared__ float sp[P_DIM];
    __shared__ float hid[H_DIM];
    __shared__ float lg[C_DIM];
    __shared__ float lse;
    int g = blockIdx.x, t = threadIdx.x;   // 64 threads
    for (int i = t; i < P_DIM; i += 64) sp[i] = d_pool[(size_t)g * P_DIM + i];
    __syncthreads();
    float acc = lin_b[t];
#pragma unroll 8
    for (int k = 0; k < P_DIM; k++) acc += sp[k] * lin_w[k * H_DIM + t];
    hid[t] = fmaxf(acc, 0.f);
    __syncthreads();
    if (t < C_DIM) {
        float a = fc_b[t];
#pragma unroll
        for (int k = 0; k < H_DIM; k++) a += hid[k] * fc_w[k * C_DIM + t];
        lg[t] = a;
    }
    __syncthreads();
    if (t == 0) {
        float m = -INFINITY;
        for (int j = 0; j < C_DIM; j++) m = fmaxf(m, lg[j]);
        float s2 = 0.f;
        for (int j = 0; j < C_DIM; j++) s2 += expf(lg[j] - m);
        lse = m + logf(s2);
    }
    __syncthreads();
    if (t < C_DIM) out[(size_t)g * C_DIM + t] = lg[t] - lse;
}

// ---------------- launch ----------------------------------------
extern "C" void kernel_launch(void* const* d_in, const int* in_sizes, int n_in,
                              void* d_out, int out_size) {
    int o = (n_in >= 17) ? 0 : -1;
    const float* x       = (const float*)d_in[0];
    const int*   ei      = (const int*)d_in[1];
    const float* enorm   = (const float*)d_in[2];
    const int*   etype   = (const int*)d_in[3];
    const int*   seql    = (const int*)d_in[4];
    const float* w1_rel  = (const float*)d_in[6 + o];
    const float* w1_root = (const float*)d_in[7 + o];
    const float* b1      = (const float*)d_in[8 + o];
    const float* bases   = (const float*)d_in[9 + o];
    const float* comp    = (const float*)d_in[10 + o];
    const float* w2      = (const float*)d_in[11 + o];
    const float* b2      = (const float*)d_in[12 + o];
    const float* lin_w   = (const float*)d_in[13 + o];
    const float* lin_b   = (const float*)d_in[14 + o];
    const float* fc_w    = (const float*)d_in[15 + o];
    const float* fc_b    = (const float*)d_in[16 + o];

    int N  = in_sizes[0] / F_DIM;
    int E  = in_sizes[2];
    int G  = in_sizes[4];
    int NB = in_sizes[9 + o] / (H_DIM * H_DIM);
    int R  = in_sizes[10 + o] / NB;
    float* out = (float*)d_out;
    (void)out_size;

    static cudaStream_t sA = 0, sB = 0;
    static cudaEvent_t evRoot = 0, evA = 0, evB = 0;
    if (sA == 0) {
        cudaStreamCreateWithFlags(&sA, cudaStreamNonBlocking);
        cudaStreamCreateWithFlags(&sB, cudaStreamNonBlocking);
        cudaEventCreateWithFlags(&evRoot, cudaEventDisableTiming);
        cudaEventCreateWithFlags(&evA, cudaEventDisableTiming);
        cudaEventCreateWithFlags(&evB, cudaEventDisableTiming);
        cudaFuncSetAttribute(k_proj, cudaFuncAttributeMaxDynamicSharedMemorySize, 81920);
    }

    int chunk  = (E + NBLK_B - 1) / NBLK_B;
    int dchunk = (N + DSCAN_B - 1) / DSCAN_B;

    // fork
    cudaEventRecord(evRoot, 0);
    cudaStreamWaitEvent(sA, evRoot, 0);
    cudaStreamWaitEvent(sB, evRoot, 0);

    // stream A: all edge bucketing (independent of proj)
    k_prep<<<2048, 256, 0, sA>>>(comp, bases, R, NB, N);
    k_hist<<<NBLK_B, 256, 0, sA>>>(ei, etype, E, R, chunk);
    k_bscan<<<1, 1024, 0, sA>>>(R, E);
    k_scatter<<<NBLK_B, 256, 0, sA>>>(ei, etype, E, R, chunk);
    k_dscan1<<<DSCAN_B, 512, 0, sA>>>(N, dchunk);
    k_dscan2<<<1, DSCAN_B, 0, sA>>>(E, N);
    k_dscan3<<<DSCAN_B, 256, 0, sA>>>(N, dchunk);
    k_dscatter<<<512, 256, 0, sA>>>(ei, enorm, E);
    cudaEventRecord(evA, sA);

    // stream B: graph offsets + x-half of pooling
    k_scan<<<1, 1024, 0, sB>>>(seql, G);
    k_pool_x<<<G, 128, 0, sB>>>(x, G);
    cudaEventRecord(evB, sB);

    // main stream: critical path
    k_proj<<<444, 256, 81920>>>(x, w1_rel, w1_root, b1, N);
    cudaStreamWaitEvent(0, evA, 0);
    k_agg1b<<<(N + 7) / 8, 256>>>(N);
    k_oroot<<<592, 256>>>(w2, b2, N);
    k_rgcn3<<<R * 64, 256>>>(R);
    k_pool_o<<<G, 64>>>(G);
    cudaStreamWaitEvent(0, evB, 0);
    k_head<<<G, 64>>>(lin_w, lin_b, fc_w, fc_b, out, G);
}

// round 11
// speedup vs baseline: 2.0422x; 1.0446x over previous
#include <cuda_runtime.h>
#include <cuda_bf16.h>
#include <math.h>

// ---------------- compile-time architecture dims ----------------
#define F_DIM 128
#define H_DIM 64
#define C_DIM 10
#define P_DIM 384           // 2*(F+H)
#define N_CAP 100000
#define R_CAP 16
#define G_CAP 1024
#define E_CAP 1000000
#define NBLK_B 512          // blocks for hist/scatter passes
#define DSCAN_B 256         // blocks for dst scan

// ---------------- scratch (static device arrays; no allocs) -----
__device__ float d_W[R_CAP * H_DIM * H_DIM];   // 256 KB  [r][k][n]
__device__ float d_y[(size_t)N_CAP * H_DIM];   // 25.6 MB  x @ w1_rel
__device__ float d_h[(size_t)N_CAP * H_DIM];   // 25.6 MB  node hidden
__device__ float d_o[(size_t)N_CAP * H_DIM];   // 25.6 MB  root-transform out
__device__ float d_o2[(size_t)N_CAP * H_DIM];  // 25.6 MB  rgcn message out
__device__ int   d_cnt[(size_t)N_CAP * R_CAP]; // 6.4 MB   per (node, rel) counts
__device__ float d_pool[(size_t)G_CAP * P_DIM];
__device__ int   d_offs[G_CAP + 1];
// relation bucketing (for k_rgcn3)
__device__ int2  d_bedge[E_CAP];               // (src, dst) sorted by relation
__device__ int   d_bhist[R_CAP * NBLK_B];
__device__ int   d_boff [R_CAP * NBLK_B];
__device__ int   d_bstart[R_CAP];
__device__ int   d_bcnt  [R_CAP];
// dst bucketing (for k_agg1b, atomic-free aggregation)
__device__ int2  d_dedge[E_CAP];               // (src, nrm_bits) sorted by dst
__device__ int   d_dcnt[N_CAP];
__device__ int   d_doff[N_CAP + 1];
__device__ int   d_dcur[N_CAP];
__device__ int   d_dpartial[DSCAN_B];

// ---------------- vector reductions (sm_90+) --------------------
__device__ __forceinline__ void red_add_v2(float* addr, float a, float b) {
    asm volatile("red.global.add.v2.f32 [%0], {%1, %2};"
                 :: "l"(addr), "f"(a), "f"(b) : "memory");
}

// ---------------- tf32 mma helpers ------------------------------
__device__ __forceinline__ unsigned f2tf32(float x) {
    unsigned r;
    asm("cvt.rna.tf32.f32 %0, %1;" : "=r"(r) : "f"(x));
    return r;
}
__device__ __forceinline__ void mma_tf32(float& c0, float& c1, float& c2, float& c3,
                                         unsigned a0, unsigned a1, unsigned a2, unsigned a3,
                                         unsigned b0, unsigned b1) {
    asm volatile("mma.sync.aligned.m16n8k8.row.col.f32.tf32.tf32.f32 "
                 "{%0,%1,%2,%3}, {%4,%5,%6,%7}, {%8,%9}, {%0,%1,%2,%3};"
                 : "+f"(c0), "+f"(c1), "+f"(c2), "+f"(c3)
                 : "r"(a0), "r"(a1), "r"(a2), "r"(a3), "r"(b0), "r"(b1));
}

// ---------------- k_prep: zero counts + o2, W = comp @ bases ----
__global__ void k_prep(const float* __restrict__ comp, const float* __restrict__ bases,
                       int R, int NB, int N) {
    int tid = blockIdx.x * blockDim.x + threadIdx.x;
    int nth = gridDim.x * blockDim.x;
    int total_cnt = N * R;
    for (int i = tid; i < total_cnt; i += nth) d_cnt[i] = 0;
    for (int i = tid; i < N; i += nth) d_dcnt[i] = 0;
    size_t no = (size_t)N * H_DIM;
    for (size_t i = tid; i < no; i += nth) d_o2[i] = 0.f;
    int wtot = R * H_DIM * H_DIM;
    for (int i = tid; i < wtot; i += nth) {
        int r = i >> 12;          // / 4096
        int ij = i & 4095;
        float acc = 0.f;
        for (int b = 0; b < NB; b++)
            acc += comp[r * NB + b] * bases[b * 4096 + ij];
        d_W[i] = acc;
    }
}

// ---------------- k_scan: exclusive prefix of seq_lengths -------
__global__ void k_scan(const int* __restrict__ sl, int G) {
    __shared__ int s[1024];
    int t = threadIdx.x;
    s[t] = (t < G) ? sl[t] : 0;
    __syncthreads();
    for (int off = 1; off < 1024; off <<= 1) {
        int add = (t >= off) ? s[t - off] : 0;
        __syncthreads();
        s[t] += add;
        __syncthreads();
    }
    if (t == 0) d_offs[0] = 0;
    if (t < G) d_offs[t + 1] = s[t];
}

// ---------------- k_proj_mma: [y|h] = x @ [w_rel|w_root] (+b1) --
// tf32 3-term split, persistent 148 blocks, W^T hi/lo in 135KB smem
__global__ __launch_bounds__(512, 1) void k_proj_mma(
    const float* __restrict__ x, const float* __restrict__ w_rel,
    const float* __restrict__ w_root, const float* __restrict__ b1, int N) {
    extern __shared__ unsigned sm[];
    unsigned* sWhi = sm;                 // [n 0..127][k stride 132]
    unsigned* sWlo = sm + 128 * 132;
    for (int i = threadIdx.x; i < 128 * 128; i += 512) {
        int n = i >> 7, k = i & 127;
        float v = (n < 64) ? w_rel[k * 64 + n] : w_root[k * 64 + (n - 64)];
        unsigned hi = f2tf32(v);
        sWhi[n * 132 + k] = hi;
        sWlo[n * 132 + k] = f2tf32(v - __uint_as_float(hi));
    }
    __syncthreads();
    int lane = threadIdx.x & 31, wl = threadIdx.x >> 5;
    int gID = lane >> 2, tig = lane & 3;
    int warp = blockIdx.x * 16 + wl;
    int nwarp = gridDim.x * 16;
    int ntiles = (N + 15) >> 4;
    for (int tile = warp; tile < ntiles; tile += nwarp) {
        int r_lo = tile * 16 + gID;
        int r_hi = r_lo + 8;
        const float* xlo = x + (size_t)min(r_lo, N - 1) * F_DIM;
        const float* xhi = x + (size_t)min(r_hi, N - 1) * F_DIM;
        float acc[16][4];
#pragma unroll
        for (int i = 0; i < 16; i++) {
            acc[i][0] = 0.f; acc[i][1] = 0.f; acc[i][2] = 0.f; acc[i][3] = 0.f;
        }
#pragma unroll 4
        for (int kt = 0; kt < 16; kt++) {
            int kb = kt * 8 + tig;
            float f0 = xlo[kb], f1 = xhi[kb], f2 = xlo[kb + 4], f3 = xhi[kb + 4];
            unsigned a0h = f2tf32(f0), a1h = f2tf32(f1);
            unsigned a2h = f2tf32(f2), a3h = f2tf32(f3);
            unsigned a0l = f2tf32(f0 - __uint_as_float(a0h));
            unsigned a1l = f2tf32(f1 - __uint_as_float(a1h));
            unsigned a2l = f2tf32(f2 - __uint_as_float(a2h));
            unsigned a3l = f2tf32(f3 - __uint_as_float(a3h));
#pragma unroll
            for (int nt = 0; nt < 16; nt++) {
                const unsigned* bh = sWhi + (nt * 8 + gID) * 132 + kt * 8;
                const unsigned* bl = sWlo + (nt * 8 + gID) * 132 + kt * 8;
                unsigned b0h = bh[tig], b1h = bh[tig + 4];
                unsigned b0l = bl[tig], b1l = bl[tig + 4];
                mma_tf32(acc[nt][0], acc[nt][1], acc[nt][2], acc[nt][3],
                         a0h, a1h, a2h, a3h, b0h, b1h);
                mma_tf32(acc[nt][0], acc[nt][1], acc[nt][2], acc[nt][3],
                         a0h, a1h, a2h, a3h, b0l, b1l);
                mma_tf32(acc[nt][0], acc[nt][1], acc[nt][2], acc[nt][3],
                         a0l, a1l, a2l, a3l, b0h, b1h);
            }
        }
        bool ok_lo = r_lo < N, ok_hi = r_hi < N;
#pragma unroll
        for (int nt = 0; nt < 16; nt++) {
            int col = (nt & 7) * 8 + 2 * tig;
            if (nt < 8) {
                if (ok_lo)
                    *(float2*)(d_y + (size_t)r_lo * H_DIM + col) =
                        make_float2(acc[nt][0], acc[nt][1]);
                if (ok_hi)
                    *(float2*)(d_y + (size_t)r_hi * H_DIM + col) =
                        make_float2(acc[nt][2], acc[nt][3]);
            } else {
                float bb0 = b1[col], bb1 = b1[col + 1];
                if (ok_lo)
                    *(float2*)(d_h + (size_t)r_lo * H_DIM + col) =
                        make_float2(acc[nt][0] + bb0, acc[nt][1] + bb1);
                if (ok_hi)
                    *(float2*)(d_h + (size_t)r_hi * H_DIM + col) =
                        make_float2(acc[nt][2] + bb0, acc[nt][3] + bb1);
            }
        }
    }
}

// ---------------- k_hist: (dst,rel) counts + per-block rel hist + dst counts
__global__ void k_hist(const int* __restrict__ ei, const int* __restrict__ et,
                       int E, int R, int chunk) {
    __shared__ int h[R_CAP];
    int t = threadIdx.x;
    if (t < R) h[t] = 0;
    __syncthreads();
    int s = blockIdx.x * chunk;
    int e_end = min(E, s + chunk);
    for (int e = s + t; e < e_end; e += blockDim.x) {
        int dst = ei[E + e];
        int r = et[e];
        atomicAdd(&d_cnt[(size_t)dst * R + r], 1);
        atomicAdd(&d_dcnt[dst], 1);
        atomicAdd(&h[r], 1);
    }
    __syncthreads();
    if (t < R) d_bhist[t * NBLK_B + blockIdx.x] = h[t];
}

// ---------------- k_bscan: scan per-block rel histograms --------
__global__ void k_bscan(int R, int E) {
    __shared__ int ssum[1024];
    int t = threadIdx.x;
    int base = t * 8;             // 1024*8 = 8192 = R_CAP*NBLK_B
    int v[8];
    int s = 0;
#pragma unroll
    for (int i = 0; i < 8; i++) { v[i] = s; s += d_bhist[base + i]; }
    ssum[t] = s;
    __syncthreads();
    for (int off = 1; off < 1024; off <<= 1) {
        int add = (t >= off) ? ssum[t - off] : 0;
        __syncthreads();
        ssum[t] += add;
        __syncthreads();
    }
    int excl = ssum[t] - s;
#pragma unroll
    for (int i = 0; i < 8; i++) d_boff[base + i] = excl + v[i];
    if (t < R) {
        int chunks_per_rel = NBLK_B / 8;
        int st = (t == 0) ? 0 : ssum[t * chunks_per_rel - 1];
        int en = ssum[(t + 1) * chunks_per_rel - 1];
        d_bstart[t] = st;
        d_bcnt[t] = en - st;
    }
}

// ---------------- k_scatter: edges -> relation buckets ----------
__global__ void k_scatter(const int* __restrict__ ei, const int* __restrict__ et,
                          int E, int R, int chunk) {
    __shared__ int c[R_CAP];
    int t = threadIdx.x;
    if (t < R) c[t] = d_boff[t * NBLK_B + blockIdx.x];
    __syncthreads();
    int s = blockIdx.x * chunk;
    int e_end = min(E, s + chunk);
    for (int e = s + t; e < e_end; e += blockDim.x) {
        int r = et[e];
        int pos = atomicAdd(&c[r], 1);
        d_bedge[pos] = make_int2(ei[e], ei[E + e]);
    }
}

// ---------------- dst-CSR scan (3 kernels over d_dcnt[N]) ------
__global__ void k_dscan1(int N, int chunk) {
    __shared__ int s[512];
    int b = blockIdx.x, t = threadIdx.x;
    int base = b * chunk;
    int idx = base + t;
    int v = (t < chunk && idx < N) ? d_dcnt[idx] : 0;
    s[t] = v;
    __syncthreads();
    for (int off = 1; off < 512; off <<= 1) {
        int add = (t >= off) ? s[t - off] : 0;
        __syncthreads();
        s[t] += add;
        __syncthreads();
    }
    if (t < chunk && idx < N) d_doff[idx] = s[t] - v;   // local exclusive
    if (t == 511) d_dpartial[b] = s[511];
}
__global__ void k_dscan2(int E, int N) {
    __shared__ int s[DSCAN_B];
    int t = threadIdx.x;
    int v = d_dpartial[t];
    s[t] = v;
    __syncthreads();
    for (int off = 1; off < DSCAN_B; off <<= 1) {
        int add = (t >= off) ? s[t - off] : 0;
        __syncthreads();
        s[t] += add;
        __syncthreads();
    }
    d_dpartial[t] = s[t] - v;    // exclusive base per block
    if (t == 0) d_doff[N] = E;
}
__global__ void k_dscan3(int N, int chunk) {
    int b = blockIdx.x;
    int base = b * chunk;
    int add = d_dpartial[b];
    for (int i = threadIdx.x; i < chunk; i += blockDim.x) {
        int idx = base + i;
        if (idx < N) {
            int o = d_doff[idx] + add;
            d_doff[idx] = o;
            d_dcur[idx] = o;
        }
    }
}

// ---------------- k_dscatter: edges -> dst-sorted (src, nrm) ----
__global__ void k_dscatter(const int* __restrict__ ei, const float* __restrict__ nrm,
                           int E) {
    int t = blockIdx.x * blockDim.x + threadIdx.x;
    int nth = gridDim.x * blockDim.x;
    for (int e = t; e < E; e += nth) {
        int dst = ei[E + e];
        int pos = atomicAdd(&d_dcur[dst], 1);
        d_dedge[pos] = make_int2(ei[e], __float_as_int(nrm[e]));
    }
}

// ---------------- k_agg1b: warp per dst, NO atomics -------------
__global__ void k_agg1b(int N) {
    int lane = threadIdx.x & 31;
    int d = (blockIdx.x * blockDim.x + threadIdx.x) >> 5;
    if (d >= N) return;
    int s = d_doff[d], e2 = d_doff[d + 1];
    float* hp = d_h + (size_t)d * H_DIM + 2 * lane;
    float2 acc = *(float2*)hp;
    int i = s;
    for (; i + 2 <= e2; i += 2) {
        int2 a = d_dedge[i];
        int2 b = d_dedge[i + 1];
        float2 y0 = *(const float2*)(d_y + (size_t)a.x * H_DIM + 2 * lane);
        float2 y1 = *(const float2*)(d_y + (size_t)b.x * H_DIM + 2 * lane);
        float w0 = __int_as_float(a.y), w1 = __int_as_float(b.y);
        acc.x += y0.x * w0; acc.y += y0.y * w0;
        acc.x += y1.x * w1; acc.y += y1.y * w1;
    }
    if (i < e2) {
        int2 a = d_dedge[i];
        float2 y0 = *(const float2*)(d_y + (size_t)a.x * H_DIM + 2 * lane);
        float w0 = __int_as_float(a.y);
        acc.x += y0.x * w0; acc.y += y0.y * w0;
    }
    *(float2*)hp = acc;
}

// ---------------- k_oroot_mma: o = h @ w2_root + b2 (tf32 MMA) --
__global__ __launch_bounds__(256) void k_oroot_mma(
    const float* __restrict__ w2, const float* __restrict__ b2, int N) {
    __shared__ unsigned sWhi[64 * 68];   // W^T [n][k] stride 68
    __shared__ unsigned sWlo[64 * 68];
    for (int i = threadIdx.x; i < 64 * 64; i += 256) {
        int n = i >> 6, k = i & 63;
        float v = w2[k * 64 + n];
        unsigned hi = f2tf32(v);
        sWhi[n * 68 + k] = hi;
        sWlo[n * 68 + k] = f2tf32(v - __uint_as_float(hi));
    }
    __syncthreads();
    int lane = threadIdx.x & 31, wl = threadIdx.x >> 5;
    int gID = lane >> 2, tig = lane & 3;
    int warp = blockIdx.x * 8 + wl;
    int nwarp = gridDim.x * 8;
    int ntiles = (N + 15) >> 4;
    for (int tile = warp; tile < ntiles; tile += nwarp) {
        int r_lo = tile * 16 + gID;
        int r_hi = r_lo + 8;
        const float* hlo = d_h + (size_t)min(r_lo, N - 1) * H_DIM;
        const float* hhi = d_h + (size_t)min(r_hi, N - 1) * H_DIM;
        float acc[8][4];
#pragma unroll
        for (int i = 0; i < 8; i++) {
            acc[i][0] = 0.f; acc[i][1] = 0.f; acc[i][2] = 0.f; acc[i][3] = 0.f;
        }
#pragma unroll
        for (int kt = 0; kt < 8; kt++) {
            int kb = kt * 8 + tig;
            float f0 = hlo[kb], f1 = hhi[kb], f2 = hlo[kb + 4], f3 = hhi[kb + 4];
            unsigned a0h = f2tf32(f0), a1h = f2tf32(f1);
            unsigned a2h = f2tf32(f2), a3h = f2tf32(f3);
            unsigned a0l = f2tf32(f0 - __uint_as_float(a0h));
            unsigned a1l = f2tf32(f1 - __uint_as_float(a1h));
            unsigned a2l = f2tf32(f2 - __uint_as_float(a2h));
            unsigned a3l = f2tf32(f3 - __uint_as_float(a3h));
#pragma unroll
            for (int nt = 0; nt < 8; nt++) {
                const unsigned* bh = sWhi + (nt * 8 + gID) * 68 + kt * 8;
                const unsigned* bl = sWlo + (nt * 8 + gID) * 68 + kt * 8;
                unsigned b0h = bh[tig], b1h = bh[tig + 4];
                unsigned b0l = bl[tig], b1l = bl[tig + 4];
                mma_tf32(acc[nt][0], acc[nt][1], acc[nt][2], acc[nt][3],
                         a0h, a1h, a2h, a3h, b0h, b1h);
                mma_tf32(acc[nt][0], acc[nt][1], acc[nt][2], acc[nt][3],
                         a0h, a1h, a2h, a3h, b0l, b1l);
                mma_tf32(acc[nt][0], acc[nt][1], acc[nt][2], acc[nt][3],
                         a0l, a1l, a2l, a3l, b0h, b1h);
            }
        }
        bool ok_lo = r_lo < N, ok_hi = r_hi < N;
#pragma unroll
        for (int nt = 0; nt < 8; nt++) {
            int col = nt * 8 + 2 * tig;
            float bb0 = b2[col], bb1 = b2[col + 1];
            if (ok_lo)
                *(float2*)(d_o + (size_t)r_lo * H_DIM + col) =
                    make_float2(acc[nt][0] + bb0, acc[nt][1] + bb1);
            if (ok_hi)
                *(float2*)(d_o + (size_t)r_hi * H_DIM + col) =
                    make_float2(acc[nt][2] + bb0, acc[nt][3] + bb1);
        }
    }
}

// ---------------- k_rgcn3: bucketed tf32 MMA, 16 edges/warp -----
// o2[dst] += (h[src] @ W[rel]) / cnt[dst,rel]
__global__ __launch_bounds__(256) void k_rgcn3(int R) {
    __shared__ unsigned sWhi[64 * 68];
    __shared__ unsigned sWlo[64 * 68];
    int rel = blockIdx.x % R;
    int chunk = blockIdx.x / R;
    int nchunk = gridDim.x / R;
    const float* __restrict__ W = d_W + (size_t)rel * 4096;
    for (int i = threadIdx.x; i < 4096; i += 256) {
        int k = i >> 6, n = i & 63;
        float v = W[i];
        unsigned hi = f2tf32(v);
        float lo = v - __uint_as_float(hi);
        sWhi[n * 68 + k] = hi;
        sWlo[n * 68 + k] = f2tf32(lo);
    }
    __syncthreads();
    int start = d_bstart[rel], cnt = d_bcnt[rel];
    int lane = threadIdx.x & 31, wl = threadIdx.x >> 5;
    int gID = lane >> 2, tig = lane & 3;
    int ngroups = (cnt + 15) >> 4;
    int wstride = nchunk * 8;
    for (int g = chunk * 8 + wl; g < ngroups; g += wstride) {
        int base = start + g * 16;
        int m = min(16, cnt - g * 16);
        int2 ev = make_int2(0, 0);
        float invv = 0.f;
        if (lane < 16) {
            ev = d_bedge[base + min(lane, m - 1)];
            int c = d_cnt[(size_t)ev.y * R + rel];
            invv = 1.f / (float)(c > 1 ? c : 1);
        }
        int s_lo  = __shfl_sync(0xffffffffu, ev.x, gID);
        int s_hi  = __shfl_sync(0xffffffffu, ev.x, gID + 8);
        int d_lo  = __shfl_sync(0xffffffffu, ev.y, gID);
        int d_hi  = __shfl_sync(0xffffffffu, ev.y, gID + 8);
        float ilo = __shfl_sync(0xffffffffu, invv, gID);
        float ihi = __shfl_sync(0xffffffffu, invv, gID + 8);
        unsigned Ah[8][4], Al[8][4];
        const float* rl = d_h + (size_t)s_lo * H_DIM;
        const float* rh = d_h + (size_t)s_hi * H_DIM;
#pragma unroll
        for (int kt = 0; kt < 8; kt++) {
            float f0 = rl[kt * 8 + tig];
            float f1 = rh[kt * 8 + tig];
            float f2 = rl[kt * 8 + tig + 4];
            float f3 = rh[kt * 8 + tig + 4];
            Ah[kt][0] = f2tf32(f0); Al[kt][0] = f2tf32(f0 - __uint_as_float(Ah[kt][0]));
            Ah[kt][1] = f2tf32(f1); Al[kt][1] = f2tf32(f1 - __uint_as_float(Ah[kt][1]));
            Ah[kt][2] = f2tf32(f2); Al[kt][2] = f2tf32(f2 - __uint_as_float(Ah[kt][2]));
            Ah[kt][3] = f2tf32(f3); Al[kt][3] = f2tf32(f3 - __uint_as_float(Ah[kt][3]));
        }
#pragma unroll
        for (int nt = 0; nt < 8; nt++) {
            float c0 = 0.f, c1 = 0.f, c2 = 0.f, c3 = 0.f;
            const unsigned* bh = sWhi + (nt * 8 + gID) * 68;
            const unsigned* bl = sWlo + (nt * 8 + gID) * 68;
#pragma unroll
            for (int kt = 0; kt < 8; kt++) {
                unsigned b0h = bh[kt * 8 + tig];
                unsigned b1h = bh[kt * 8 + tig + 4];
                unsigned b0l = bl[kt * 8 + tig];
                unsigned b1l = bl[kt * 8 + tig + 4];
                mma_tf32(c0, c1, c2, c3, Ah[kt][0], Ah[kt][1], Ah[kt][2], Ah[kt][3], b0h, b1h);
                mma_tf32(c0, c1, c2, c3, Ah[kt][0], Ah[kt][1], Ah[kt][2], Ah[kt][3], b0l, b1l);
                mma_tf32(c0, c1, c2, c3, Al[kt][0], Al[kt][1], Al[kt][2], Al[kt][3], b0h, b1h);
            }
            int colg = nt * 8 + 2 * tig;
            if (gID < m)
                red_add_v2(d_o2 + (size_t)d_lo * H_DIM + colg, c0 * ilo, c1 * ilo);
            if (gID + 8 < m)
                red_add_v2(d_o2 + (size_t)d_hi * H_DIM + colg, c2 * ihi, c3 * ihi);
        }
    }
}

// ---------------- k_pool_x: per-graph sum+max over x dims -------
__global__ void k_pool_x(const float* __restrict__ x, int G) {
    int g = blockIdx.x;
    int s = d_offs[g], e = d_offs[g + 1];
    int d = threadIdx.x;                 // 128 threads
    float sum = 0.f, mx = -INFINITY;
#pragma unroll 4
    for (int n = s; n < e; n++) {
        float v = x[(size_t)n * F_DIM + d];
        sum += v; mx = fmaxf(mx, v);
    }
    d_pool[(size_t)g * P_DIM + d] = sum;
    d_pool[(size_t)g * P_DIM + 192 + d] = mx;
}

// ---------------- k_pool_o: per-graph sum+max over (o + o2) -----
__global__ void k_pool_o(int G) {
    int g = blockIdx.x;
    int s = d_offs[g], e = d_offs[g + 1];
    int t = threadIdx.x;                 // 64 threads
    float sum = 0.f, mx = -INFINITY;
#pragma unroll 4
    for (int n = s; n < e; n++) {
        float v = d_o[(size_t)n * H_DIM + t] + d_o2[(size_t)n * H_DIM + t];
        sum += v; mx = fmaxf(mx, v);
    }
    d_pool[(size_t)g * P_DIM + 128 + t] = sum;
    d_pool[(size_t)g * P_DIM + 320 + t] = mx;
}

// ---------------- k_head: linear->relu->linear->log_softmax -----
__global__ void k_head(const float* __restrict__ lin_w, const float* __restrict__ lin_b,
                       const float* __restrict__ fc_w, const float* __restrict__ fc_b,
                       float* __restrict__ out, int G) {
    __shared__ float sp[P_DIM];
    __shared__ float hid[H_DIM];
    __shared__ float lg[C_DIM];
    __shared__ float lse;
    int g = blockIdx.x, t = threadIdx.x;   // 64 threads
    for (int i = t; i < P_DIM; i += 64) sp[i] = d_pool[(size_t)g * P_DIM + i];
    __syncthreads();
    float acc = lin_b[t];
#pragma unroll 8
    for (int k = 0; k < P_DIM; k++) acc += sp[k] * lin_w[k * H_DIM + t];
    hid[t] = fmaxf(acc, 0.f);
    __syncthreads();
    if (t < C_DIM) {
        float a = fc_b[t];
#pragma unroll
        for (int k = 0; k < H_DIM; k++) a += hid[k] * fc_w[k * C_DIM + t];
        lg[t] = a;
    }
    __syncthreads();
    if (t == 0) {
        float m = -INFINITY;
        for (int j = 0; j < C_DIM; j++) m = fmaxf(m, lg[j]);
        float s2 = 0.f;
        for (int j = 0; j < C_DIM; j++) s2 += expf(lg[j] - m);
        lse = m + logf(s2);
    }
    __syncthreads();
    if (t < C_DIM) out[(size_t)g * C_DIM + t] = lg[t] - lse;
}

// ---------------- launch ----------------------------------------
extern "C" void kernel_launch(void* const* d_in, const int* in_sizes, int n_in,
                              void* d_out, int out_size) {
    int o = (n_in >= 17) ? 0 : -1;
    const float* x       = (const float*)d_in[0];
    const int*   ei      = (const int*)d_in[1];
    const float* enorm   = (const float*)d_in[2];
    const int*   etype   = (const int*)d_in[3];
    const int*   seql    = (const int*)d_in[4];
    const float* w1_rel  = (const float*)d_in[6 + o];
    const float* w1_root = (const float*)d_in[7 + o];
    const float* b1      = (const float*)d_in[8 + o];
    const float* bases   = (const float*)d_in[9 + o];
    const float* comp    = (const float*)d_in[10 + o];
    const float* w2      = (const float*)d_in[11 + o];
    const float* b2      = (const float*)d_in[12 + o];
    const float* lin_w   = (const float*)d_in[13 + o];
    const float* lin_b   = (const float*)d_in[14 + o];
    const float* fc_w    = (const float*)d_in[15 + o];
    const float* fc_b    = (const float*)d_in[16 + o];

    int N  = in_sizes[0] / F_DIM;
    int E  = in_sizes[2];
    int G  = in_sizes[4];
    int NB = in_sizes[9 + o] / (H_DIM * H_DIM);
    int R  = in_sizes[10 + o] / NB;
    float* out = (float*)d_out;
    (void)out_size;

    static cudaStream_t sA = 0, sB = 0;
    static cudaEvent_t evRoot = 0, evA = 0, evH = 0, evB2 = 0;
    if (sA == 0) {
        cudaStreamCreateWithFlags(&sA, cudaStreamNonBlocking);
        cudaStreamCreateWithFlags(&sB, cudaStreamNonBlocking);
        cudaEventCreateWithFlags(&evRoot, cudaEventDisableTiming);
        cudaEventCreateWithFlags(&evA, cudaEventDisableTiming);
        cudaEventCreateWithFlags(&evH, cudaEventDisableTiming);
        cudaEventCreateWithFlags(&evB2, cudaEventDisableTiming);
        cudaFuncSetAttribute(k_proj_mma, cudaFuncAttributeMaxDynamicSharedMemorySize,
                             128 * 132 * 2 * 4);
    }

    int chunk  = (E + NBLK_B - 1) / NBLK_B;
    int dchunk = (N + DSCAN_B - 1) / DSCAN_B;

    // fork
    cudaEventRecord(evRoot, 0);
    cudaStreamWaitEvent(sA, evRoot, 0);
    cudaStreamWaitEvent(sB, evRoot, 0);

    // stream A: all edge bucketing (independent of proj)
    k_prep<<<2048, 256, 0, sA>>>(comp, bases, R, NB, N);
    k_hist<<<NBLK_B, 256, 0, sA>>>(ei, etype, E, R, chunk);
    k_bscan<<<1, 1024, 0, sA>>>(R, E);
    k_scatter<<<NBLK_B, 256, 0, sA>>>(ei, etype, E, R, chunk);
    k_dscan1<<<DSCAN_B, 512, 0, sA>>>(N, dchunk);
    k_dscan2<<<1, DSCAN_B, 0, sA>>>(E, N);
    k_dscan3<<<DSCAN_B, 256, 0, sA>>>(N, dchunk);
    k_dscatter<<<512, 256, 0, sA>>>(ei, enorm, E);
    cudaEventRecord(evA, sA);

    // stream B: graph offsets + x-half of pooling
    k_scan<<<1, 1024, 0, sB>>>(seql, G);
    k_pool_x<<<G, 128, 0, sB>>>(x, G);

    // main stream: critical path
    k_proj_mma<<<148, 512, 128 * 132 * 2 * 4>>>(x, w1_rel, w1_root, b1, N);
    cudaStreamWaitEvent(0, evA, 0);
    k_agg1b<<<(N + 7) / 8, 256>>>(N);
    cudaEventRecord(evH, 0);

    // stream B: root transform runs concurrently with rgcn3
    cudaStreamWaitEvent(sB, evH, 0);
    k_oroot_mma<<<296, 256, 0, sB>>>(w2, b2, N);
    cudaEventRecord(evB2, sB);

    // main: rgcn messages into d_o2
    k_rgcn3<<<R * 64, 256>>>(R);
    cudaStreamWaitEvent(0, evB2, 0);
    k_pool_o<<<G, 64>>>(G);
    k_head<<<G, 64>>>(lin_w, lin_b, fc_w, fc_b, out, G);
}

// round 15
// speedup vs baseline: 2.1474x; 1.0515x over previous
#include <cuda_runtime.h>
#include <cuda_bf16.h>
#include <math.h>

// ---------------- compile-time architecture dims ----------------
#define F_DIM 128
#define H_DIM 64
#define C_DIM 10
#define P_DIM 384           // 2*(F+H)
#define N_CAP 100000
#define R_CAP 16
#define G_CAP 1024
#define E_CAP 1000000
#define NBLK_B 512          // blocks for hist/scatter passes
#define DSCAN_B 256         // blocks for dst scan

// ---------------- scratch (static device arrays; no allocs) -----
__device__ float d_W[R_CAP * H_DIM * H_DIM];   // 256 KB  [r][k][n]
__device__ float d_y[(size_t)N_CAP * H_DIM];   // 25.6 MB  x @ w1_rel
__device__ float d_h[(size_t)N_CAP * H_DIM];   // 25.6 MB  node hidden
__device__ float d_o[(size_t)N_CAP * H_DIM];   // 25.6 MB  root-transform out
__device__ float d_o2[(size_t)N_CAP * H_DIM];  // 25.6 MB  rgcn message out
__device__ int   d_cnt[(size_t)N_CAP * R_CAP]; // 6.4 MB   per (node, rel) counts
__device__ float d_pool[(size_t)G_CAP * P_DIM];
__device__ int   d_offs[G_CAP + 1];
// relation bucketing (for k_rgcn3)
__device__ int2  d_bedge[E_CAP];               // (src, dst) sorted by relation
__device__ int   d_bhist[R_CAP * NBLK_B];
__device__ int   d_boff [R_CAP * NBLK_B];
__device__ int   d_bstart[R_CAP];
__device__ int   d_bcnt  [R_CAP];
// dst bucketing (for k_agg1b, atomic-free aggregation)
__device__ int2  d_dedge[E_CAP];               // (src, nrm_bits) sorted by dst
__device__ int   d_dcnt[N_CAP];
__device__ int   d_doff[N_CAP + 1];
__device__ int   d_dcur[N_CAP];
__device__ int   d_dpartial[DSCAN_B];

// ---------------- vector reductions (sm_90+) --------------------
__device__ __forceinline__ void red_add_v2(float* addr, float a, float b) {
    asm volatile("red.global.add.v2.f32 [%0], {%1, %2};"
                 :: "l"(addr), "f"(a), "f"(b) : "memory");
}

// ---------------- tf32 mma helpers ------------------------------
__device__ __forceinline__ unsigned f2tf32(float x) {
    unsigned r;
    asm("cvt.rna.tf32.f32 %0, %1;" : "=r"(r) : "f"(x));
    return r;
}
__device__ __forceinline__ void mma_tf32(float& c0, float& c1, float& c2, float& c3,
                                         unsigned a0, unsigned a1, unsigned a2, unsigned a3,
                                         unsigned b0, unsigned b1) {
    asm volatile("mma.sync.aligned.m16n8k8.row.col.f32.tf32.tf32.f32 "
                 "{%0,%1,%2,%3}, {%4,%5,%6,%7}, {%8,%9}, {%0,%1,%2,%3};"
                 : "+f"(c0), "+f"(c1), "+f"(c2), "+f"(c3)
                 : "r"(a0), "r"(a1), "r"(a2), "r"(a3), "r"(b0), "r"(b1));
}

// ---------------- k_prep: zero counts + o2, W = comp @ bases ----
__global__ void k_prep(const float* __restrict__ comp, const float* __restrict__ bases,
                       int R, int NB, int N) {
    int tid = blockIdx.x * blockDim.x + threadIdx.x;
    int nth = gridDim.x * blockDim.x;
    int total_cnt = N * R;
    for (int i = tid; i < total_cnt; i += nth) d_cnt[i] = 0;
    for (int i = tid; i < N; i += nth) d_dcnt[i] = 0;
    size_t no = (size_t)N * H_DIM;
    for (size_t i = tid; i < no; i += nth) d_o2[i] = 0.f;
    int wtot = R * H_DIM * H_DIM;
    for (int i = tid; i < wtot; i += nth) {
        int r = i >> 12;          // / 4096
        int ij = i & 4095;
        float acc = 0.f;
        for (int b = 0; b < NB; b++)
            acc += comp[r * NB + b] * bases[b * 4096 + ij];
        d_W[i] = acc;
    }
}

// ---------------- k_scan: exclusive prefix of seq_lengths -------
__global__ void k_scan(const int* __restrict__ sl, int G) {
    __shared__ int s[1024];
    int t = threadIdx.x;
    s[t] = (t < G) ? sl[t] : 0;
    __syncthreads();
    for (int off = 1; off < 1024; off <<= 1) {
        int add = (t >= off) ? s[t - off] : 0;
        __syncthreads();
        s[t] += add;
        __syncthreads();
    }
    if (t == 0) d_offs[0] = 0;
    if (t < G) d_offs[t + 1] = s[t];
}

// ---------------- k_proj_mma: [y|h] = x @ [w_rel|w_root] (+b1) --
// tf32 3-term split; b-fragments paired as uint2 (k, k+4) -> one LDS.64.
// uint2 row stride 68 (=136 words; 136 mod 32 = 8 -> conflict-free).
__global__ __launch_bounds__(512, 1) void k_proj_mma(
    const float* __restrict__ x, const float* __restrict__ w_rel,
    const float* __restrict__ w_root, const float* __restrict__ b1, int N) {
    extern __shared__ uint2 smp[];
    uint2* sPhi = smp;                   // [n 0..127][kt*4+tig], stride 68
    uint2* sPlo = smp + 128 * 68;
    for (int i = threadIdx.x; i < 128 * 64; i += 512) {
        int n = i >> 6, j = i & 63;      // j = kt*4 + tig
        int kt = j >> 2, tig = j & 3;
        int k1 = kt * 8 + tig, k2 = k1 + 4;
        float v1 = (n < 64) ? w_rel[k1 * 64 + n] : w_root[k1 * 64 + (n - 64)];
        float v2 = (n < 64) ? w_rel[k2 * 64 + n] : w_root[k2 * 64 + (n - 64)];
        unsigned h1 = f2tf32(v1), h2 = f2tf32(v2);
        sPhi[n * 68 + j] = make_uint2(h1, h2);
        sPlo[n * 68 + j] = make_uint2(f2tf32(v1 - __uint_as_float(h1)),
                                      f2tf32(v2 - __uint_as_float(h2)));
    }
    __syncthreads();
    int lane = threadIdx.x & 31, wl = threadIdx.x >> 5;
    int gID = lane >> 2, tig = lane & 3;
    int warp = blockIdx.x * 16 + wl;
    int nwarp = gridDim.x * 16;
    int ntiles = (N + 15) >> 4;
    for (int tile = warp; tile < ntiles; tile += nwarp) {
        int r_lo = tile * 16 + gID;
        int r_hi = r_lo + 8;
        const float* xlo = x + (size_t)min(r_lo, N - 1) * F_DIM;
        const float* xhi = x + (size_t)min(r_hi, N - 1) * F_DIM;
        float acc[16][4];
#pragma unroll
        for (int i = 0; i < 16; i++) {
            acc[i][0] = 0.f; acc[i][1] = 0.f; acc[i][2] = 0.f; acc[i][3] = 0.f;
        }
#pragma unroll 4
        for (int kt = 0; kt < 16; kt++) {
            int kb = kt * 8 + tig;
            float f0 = xlo[kb], f1 = xhi[kb], f2 = xlo[kb + 4], f3 = xhi[kb + 4];
            unsigned a0h = f2tf32(f0), a1h = f2tf32(f1);
            unsigned a2h = f2tf32(f2), a3h = f2tf32(f3);
            unsigned a0l = f2tf32(f0 - __uint_as_float(a0h));
            unsigned a1l = f2tf32(f1 - __uint_as_float(a1h));
            unsigned a2l = f2tf32(f2 - __uint_as_float(a2h));
            unsigned a3l = f2tf32(f3 - __uint_as_float(a3h));
#pragma unroll
            for (int nt = 0; nt < 16; nt++) {
                uint2 bh = sPhi[(nt * 8 + gID) * 68 + kt * 4 + tig];
                uint2 bl = sPlo[(nt * 8 + gID) * 68 + kt * 4 + tig];
                mma_tf32(acc[nt][0], acc[nt][1], acc[nt][2], acc[nt][3],
                         a0h, a1h, a2h, a3h, bh.x, bh.y);
                mma_tf32(acc[nt][0], acc[nt][1], acc[nt][2], acc[nt][3],
                         a0h, a1h, a2h, a3h, bl.x, bl.y);
                mma_tf32(acc[nt][0], acc[nt][1], acc[nt][2], acc[nt][3],
                         a0l, a1l, a2l, a3l, bh.x, bh.y);
            }
        }
        bool ok_lo = r_lo < N, ok_hi = r_hi < N;
#pragma unroll
        for (int nt = 0; nt < 16; nt++) {
            int col = (nt & 7) * 8 + 2 * tig;
            if (nt < 8) {
                if (ok_lo)
                    *(float2*)(d_y + (size_t)r_lo * H_DIM + col) =
                        make_float2(acc[nt][0], acc[nt][1]);
                if (ok_hi)
                    *(float2*)(d_y + (size_t)r_hi * H_DIM + col) =
                        make_float2(acc[nt][2], acc[nt][3]);
            } else {
                float bb0 = b1[col], bb1 = b1[col + 1];
                if (ok_lo)
                    *(float2*)(d_h + (size_t)r_lo * H_DIM + col) =
                        make_float2(acc[nt][0] + bb0, acc[nt][1] + bb1);
                if (ok_hi)
                    *(float2*)(d_h + (size_t)r_hi * H_DIM + col) =
                        make_float2(acc[nt][2] + bb0, acc[nt][3] + bb1);
            }
        }
    }
}

// ---------------- k_hist: (dst,rel) counts + per-block rel hist + dst counts
__global__ void k_hist(const int* __restrict__ ei, const int* __restrict__ et,
                       int E, int R, int chunk) {
    __shared__ int h[R_CAP];
    int t = threadIdx.x;
    if (t < R) h[t] = 0;
    __syncthreads();
    int s = blockIdx.x * chunk;
    int e_end = min(E, s + chunk);
    for (int e = s + t; e < e_end; e += blockDim.x) {
        int dst = ei[E + e];
        int r = et[e];
        atomicAdd(&d_cnt[(size_t)dst * R + r], 1);
        atomicAdd(&d_dcnt[dst], 1);
        atomicAdd(&h[r], 1);
    }
    __syncthreads();
    if (t < R) d_bhist[t * NBLK_B + blockIdx.x] = h[t];
}

// ---------------- k_dscan1: per-block scan of dst counts --------
__global__ void k_dscan1(int N, int chunk) {
    __shared__ int s[512];
    int b = blockIdx.x, t = threadIdx.x;
    int base = b * chunk;
    int idx = base + t;
    int v = (t < chunk && idx < N) ? d_dcnt[idx] : 0;
    s[t] = v;
    __syncthreads();
    for (int off = 1; off < 512; off <<= 1) {
        int add = (t >= off) ? s[t - off] : 0;
        __syncthreads();
        s[t] += add;
        __syncthreads();
    }
    if (t < chunk && idx < N) d_doff[idx] = s[t] - v;   // local exclusive
    if (t == 511) d_dpartial[b] = s[511];
}

// ---------------- k_fscan: block0 = rel-hist scan; block1 = dpartial scan
__global__ void k_fscan(int R, int E, int N) {
    __shared__ int ssum[1024];
    int t = threadIdx.x;
    if (blockIdx.x == 0) {
        // scan R_CAP*NBLK_B per-block histograms -> rel bucket offsets
        int base = t * 8;
        int v[8];
        int s = 0;
#pragma unroll
        for (int i = 0; i < 8; i++) { v[i] = s; s += d_bhist[base + i]; }
        ssum[t] = s;
        __syncthreads();
        for (int off = 1; off < 1024; off <<= 1) {
            int add = (t >= off) ? ssum[t - off] : 0;
            __syncthreads();
            ssum[t] += add;
            __syncthreads();
        }
        int excl = ssum[t] - s;
#pragma unroll
        for (int i = 0; i < 8; i++) d_boff[base + i] = excl + v[i];
        if (t < R) {
            int chunks_per_rel = NBLK_B / 8;
            int st = (t == 0) ? 0 : ssum[t * chunks_per_rel - 1];
            int en = ssum[(t + 1) * chunks_per_rel - 1];
            d_bstart[t] = st;
            d_bcnt[t] = en - st;
        }
    } else {
        // scan d_dpartial[DSCAN_B] -> exclusive base per dscan block
        int v = (t < DSCAN_B) ? d_dpartial[t] : 0;
        ssum[t] = v;
        __syncthreads();
        for (int off = 1; off < 1024; off <<= 1) {
            int add = (t >= off) ? ssum[t - off] : 0;
            __syncthreads();
            ssum[t] += add;
            __syncthreads();
        }
        if (t < DSCAN_B) d_dpartial[t] = ssum[t] - v;
        if (t == 0) d_doff[N] = E;
    }
}

// ---------------- k_dscan3: add block bases, init cursors -------
__global__ void k_dscan3(int N, int chunk) {
    int b = blockIdx.x;
    int base = b * chunk;
    int add = d_dpartial[b];
    for (int i = threadIdx.x; i < chunk; i += blockDim.x) {
        int idx = base + i;
        if (idx < N) {
            int o = d_doff[idx] + add;
            d_doff[idx] = o;
            d_dcur[idx] = o;
        }
    }
}

// ---------------- k_scatter2: BOTH scatters in one pass ---------
__global__ void k_scatter2(const int* __restrict__ ei, const int* __restrict__ et,
                           const float* __restrict__ nrm, int E, int R, int chunk) {
    __shared__ int c[R_CAP];
    int t = threadIdx.x;
    if (t < R) c[t] = d_boff[t * NBLK_B + blockIdx.x];
    __syncthreads();
    int s = blockIdx.x * chunk;
    int e_end = min(E, s + chunk);
    for (int e = s + t; e < e_end; e += blockDim.x) {
        int src = ei[e];
        int dst = ei[E + e];
        int r = et[e];
        int pos = atomicAdd(&c[r], 1);
        d_bedge[pos] = make_int2(src, dst);
        int pos2 = atomicAdd(&d_dcur[dst], 1);
        d_dedge[pos2] = make_int2(src, __float_as_int(nrm[e]));
    }
}

// ---------------- k_agg1b: warp per dst, NO atomics -------------
__global__ void k_agg1b(int N) {
    int lane = threadIdx.x & 31;
    int d = (blockIdx.x * blockDim.x + threadIdx.x) >> 5;
    if (d >= N) return;
    int s = d_doff[d], e2 = d_doff[d + 1];
    float* hp = d_h + (size_t)d * H_DIM + 2 * lane;
    float2 acc = *(float2*)hp;
    int i = s;
    for (; i + 2 <= e2; i += 2) {
        int2 a = d_dedge[i];
        int2 b = d_dedge[i + 1];
        float2 y0 = *(const float2*)(d_y + (size_t)a.x * H_DIM + 2 * lane);
        float2 y1 = *(const float2*)(d_y + (size_t)b.x * H_DIM + 2 * lane);
        float w0 = __int_as_float(a.y), w1 = __int_as_float(b.y);
        acc.x += y0.x * w0; acc.y += y0.y * w0;
        acc.x += y1.x * w1; acc.y += y1.y * w1;
    }
    if (i < e2) {
        int2 a = d_dedge[i];
        float2 y0 = *(const float2*)(d_y + (size_t)a.x * H_DIM + 2 * lane);
        float w0 = __int_as_float(a.y);
        acc.x += y0.x * w0; acc.y += y0.y * w0;
    }
    *(float2*)hp = acc;
}

// ---------------- k_oroot_mma: o = h @ w2_root + b2 (tf32 MMA) --
// paired-uint2 b-frags, row stride 36 uint2 (=72 words; 72 mod 32 = 8)
__global__ __launch_bounds__(256) void k_oroot_mma(
    const float* __restrict__ w2, const float* __restrict__ b2, int N) {
    __shared__ uint2 sPhi[64 * 36];
    __shared__ uint2 sPlo[64 * 36];
    for (int i = threadIdx.x; i < 64 * 32; i += 256) {
        int n = i >> 5, j = i & 31;       // j = kt*4 + tig
        int kt = j >> 2, tig = j & 3;
        int k1 = kt * 8 + tig, k2 = k1 + 4;
        float v1 = w2[k1 * 64 + n];
        float v2 = w2[k2 * 64 + n];
        unsigned h1 = f2tf32(v1), h2 = f2tf32(v2);
        sPhi[n * 36 + j] = make_uint2(h1, h2);
        sPlo[n * 36 + j] = make_uint2(f2tf32(v1 - __uint_as_float(h1)),
                                      f2tf32(v2 - __uint_as_float(h2)));
    }
    __syncthreads();
    int lane = threadIdx.x & 31, wl = threadIdx.x >> 5;
    int gID = lane >> 2, tig = lane & 3;
    int warp = blockIdx.x * 8 + wl;
    int nwarp = gridDim.x * 8;
    int ntiles = (N + 15) >> 4;
    for (int tile = warp; tile < ntiles; tile += nwarp) {
        int r_lo = tile * 16 + gID;
        int r_hi = r_lo + 8;
        const float* hlo = d_h + (size_t)min(r_lo, N - 1) * H_DIM;
        const float* hhi = d_h + (size_t)min(r_hi, N - 1) * H_DIM;
        float acc[8][4];
#pragma unroll
        for (int i = 0; i < 8; i++) {
            acc[i][0] = 0.f; acc[i][1] = 0.f; acc[i][2] = 0.f; acc[i][3] = 0.f;
        }
#pragma unroll
        for (int kt = 0; kt < 8; kt++) {
            int kb = kt * 8 + tig;
            float f0 = hlo[kb], f1 = hhi[kb], f2 = hlo[kb + 4], f3 = hhi[kb + 4];
            unsigned a0h = f2tf32(f0), a1h = f2tf32(f1);
            unsigned a2h = f2tf32(f2), a3h = f2tf32(f3);
            unsigned a0l = f2tf32(f0 - __uint_as_float(a0h));
            unsigned a1l = f2tf32(f1 - __uint_as_float(a1h));
            unsigned a2l = f2tf32(f2 - __uint_as_float(a2h));
            unsigned a3l = f2tf32(f3 - __uint_as_float(a3h));
#pragma unroll
            for (int nt = 0; nt < 8; nt++) {
                uint2 bh = sPhi[(nt * 8 + gID) * 36 + kt * 4 + tig];
                uint2 bl = sPlo[(nt * 8 + gID) * 36 + kt * 4 + tig];
                mma_tf32(acc[nt][0], acc[nt][1], acc[nt][2], acc[nt][3],
                         a0h, a1h, a2h, a3h, bh.x, bh.y);
                mma_tf32(acc[nt][0], acc[nt][1], acc[nt][2], acc[nt][3],
                         a0h, a1h, a2h, a3h, bl.x, bl.y);
                mma_tf32(acc[nt][0], acc[nt][1], acc[nt][2], acc[nt][3],
                         a0l, a1l, a2l, a3l, bh.x, bh.y);
            }
        }
        bool ok_lo = r_lo < N, ok_hi = r_hi < N;
#pragma unroll
        for (int nt = 0; nt < 8; nt++) {
            int col = nt * 8 + 2 * tig;
            float bb0 = b2[col], bb1 = b2[col + 1];
            if (ok_lo)
                *(float2*)(d_o + (size_t)r_lo * H_DIM + col) =
                    make_float2(acc[nt][0] + bb0, acc[nt][1] + bb1);
            if (ok_hi)
                *(float2*)(d_o + (size_t)r_hi * H_DIM + col) =
                    make_float2(acc[nt][2] + bb0, acc[nt][3] + bb1);
        }
    }
}

// ---------------- k_rgcn3: bucketed tf32 MMA, 16 edges/warp -----
// o2[dst] += (h[src] @ W[rel]) / cnt[dst,rel]; paired-uint2 b-frags
__global__ __launch_bounds__(256) void k_rgcn3(int R) {
    __shared__ uint2 sPhi[64 * 36];
    __shared__ uint2 sPlo[64 * 36];
    int rel = blockIdx.x % R;
    int chunk = blockIdx.x / R;
    int nchunk = gridDim.x / R;
    const float* __restrict__ W = d_W + (size_t)rel * 4096;
    for (int i = threadIdx.x; i < 64 * 32; i += 256) {
        int n = i >> 5, j = i & 31;
        int kt = j >> 2, tig = j & 3;
        int k1 = kt * 8 + tig, k2 = k1 + 4;
        float v1 = W[k1 * 64 + n];
        float v2 = W[k2 * 64 + n];
        unsigned h1 = f2tf32(v1), h2 = f2tf32(v2);
        sPhi[n * 36 + j] = make_uint2(h1, h2);
        sPlo[n * 36 + j] = make_uint2(f2tf32(v1 - __uint_as_float(h1)),
                                      f2tf32(v2 - __uint_as_float(h2)));
    }
    __syncthreads();
    int start = d_bstart[rel], cnt = d_bcnt[rel];
    int lane = threadIdx.x & 31, wl = threadIdx.x >> 5;
    int gID = lane >> 2, tig = lane & 3;
    int ngroups = (cnt + 15) >> 4;
    int wstride = nchunk * 8;
    for (int g = chunk * 8 + wl; g < ngroups; g += wstride) {
        int base = start + g * 16;
        int m = min(16, cnt - g * 16);
        int2 ev = make_int2(0, 0);
        float invv = 0.f;
        if (lane < 16) {
            ev = d_bedge[base + min(lane, m - 1)];
            int c = d_cnt[(size_t)ev.y * R + rel];
            invv = 1.f / (float)(c > 1 ? c : 1);
        }
        int s_lo  = __shfl_sync(0xffffffffu, ev.x, gID);
        int s_hi  = __shfl_sync(0xffffffffu, ev.x, gID + 8);
        int d_lo  = __shfl_sync(0xffffffffu, ev.y, gID);
        int d_hi  = __shfl_sync(0xffffffffu, ev.y, gID + 8);
        float ilo = __shfl_sync(0xffffffffu, invv, gID);
        float ihi = __shfl_sync(0xffffffffu, invv, gID + 8);
        unsigned Ah[8][4], Al[8][4];
        const float* rl = d_h + (size_t)s_lo * H_DIM;
        const float* rh = d_h + (size_t)s_hi * H_DIM;
#pragma unroll
        for (int kt = 0; kt < 8; kt++) {
            float f0 = rl[kt * 8 + tig];
            float f1 = rh[kt * 8 + tig];
            float f2 = rl[kt * 8 + tig + 4];
            float f3 = rh[kt * 8 + tig + 4];
            Ah[kt][0] = f2tf32(f0); Al[kt][0] = f2tf32(f0 - __uint_as_float(Ah[kt][0]));
            Ah[kt][1] = f2tf32(f1); Al[kt][1] = f2tf32(f1 - __uint_as_float(Ah[kt][1]));
            Ah[kt][2] = f2tf32(f2); Al[kt][2] = f2tf32(f2 - __uint_as_float(Ah[kt][2]));
            Ah[kt][3] = f2tf32(f3); Al[kt][3] = f2tf32(f3 - __uint_as_float(Ah[kt][3]));
        }
#pragma unroll
        for (int nt = 0; nt < 8; nt++) {
            float c0 = 0.f, c1 = 0.f, c2 = 0.f, c3 = 0.f;
#pragma unroll
            for (int kt = 0; kt < 8; kt++) {
                uint2 bh = sPhi[(nt * 8 + gID) * 36 + kt * 4 + tig];
                uint2 bl = sPlo[(nt * 8 + gID) * 36 + kt * 4 + tig];
                mma_tf32(c0, c1, c2, c3, Ah[kt][0], Ah[kt][1], Ah[kt][2], Ah[kt][3], bh.x, bh.y);
                mma_tf32(c0, c1, c2, c3, Ah[kt][0], Ah[kt][1], Ah[kt][2], Ah[kt][3], bl.x, bl.y);
                mma_tf32(c0, c1, c2, c3, Al[kt][0], Al[kt][1], Al[kt][2], Al[kt][3], bh.x, bh.y);
            }
            int colg = nt * 8 + 2 * tig;
            if (gID < m)
                red_add_v2(d_o2 + (size_t)d_lo * H_DIM + colg, c0 * ilo, c1 * ilo);
            if (gID + 8 < m)
                red_add_v2(d_o2 + (size_t)d_hi * H_DIM + colg, c2 * ihi, c3 * ihi);
        }
    }
}

// ---------------- k_pool_x: per-graph sum+max over x dims -------
__global__ void k_pool_x(const float* __restrict__ x, int G) {
    int g = blockIdx.x;
    int s = d_offs[g], e = d_offs[g + 1];
    int d = threadIdx.x;                 // 128 threads
    float sum = 0.f, mx = -INFINITY;
#pragma unroll 4
    for (int n = s; n < e; n++) {
        float v = x[(size_t)n * F_DIM + d];
        sum += v; mx = fmaxf(mx, v);
    }
    d_pool[(size_t)g * P_DIM + d] = sum;
    d_pool[(size_t)g * P_DIM + 192 + d] = mx;
}

// ---------------- k_head2: pool(o+o2) + linear->relu->linear->log_softmax
__global__ void k_head2(const float* __restrict__ lin_w, const float* __restrict__ lin_b,
                        const float* __restrict__ fc_w, const float* __restrict__ fc_b,
                        float* __restrict__ out, int G) {
    __shared__ float sp[P_DIM];
    __shared__ float hid[H_DIM];
    __shared__ float lg[C_DIM];
    __shared__ float lse;
    int g = blockIdx.x, t = threadIdx.x;   // 64 threads
    int s = d_offs[g], e = d_offs[g + 1];
    // inline pool over o + o2 (this graph's nodes)
    {
        float sum = 0.f, mx = -INFINITY;
#pragma unroll 4
        for (int n = s; n < e; n++) {
            float v = d_o[(size_t)n * H_DIM + t] + d_o2[(size_t)n * H_DIM + t];
            sum += v; mx = fmaxf(mx, v);
        }
        sp[128 + t] = sum;
        sp[320 + t] = mx;
    }
    // x-pool halves from d_pool
    for (int i = t; i < 128; i += 64) {
        sp[i] = d_pool[(size_t)g * P_DIM + i];
        sp[192 + i] = d_pool[(size_t)g * P_DIM + 192 + i];
    }
    __syncthreads();
    float acc = lin_b[t];
#pragma unroll 8
    for (int k = 0; k < P_DIM; k++) acc += sp[k] * lin_w[k * H_DIM + t];
    hid[t] = fmaxf(acc, 0.f);
    __syncthreads();
    if (t < C_DIM) {
        float a = fc_b[t];
#pragma unroll
        for (int k = 0; k < H_DIM; k++) a += hid[k] * fc_w[k * C_DIM + t];
        lg[t] = a;
    }
    __syncthreads();
    if (t == 0) {
        float m = -INFINITY;
        for (int j = 0; j < C_DIM; j++) m = fmaxf(m, lg[j]);
        float s2 = 0.f;
        for (int j = 0; j < C_DIM; j++) s2 += expf(lg[j] - m);
        lse = m + logf(s2);
    }
    __syncthreads();
    if (t < C_DIM) out[(size_t)g * C_DIM + t] = lg[t] - lse;
}

// ---------------- launch ----------------------------------------
extern "C" void kernel_launch(void* const* d_in, const int* in_sizes, int n_in,
                              void* d_out, int out_size) {
    int o = (n_in >= 17) ? 0 : -1;
    const float* x       = (const float*)d_in[0];
    const int*   ei      = (const int*)d_in[1];
    const float* enorm   = (const float*)d_in[2];
    const int*   etype   = (const int*)d_in[3];
    const int*   seql    = (const int*)d_in[4];
    const float* w1_rel  = (const float*)d_in[6 + o];
    const float* w1_root = (const float*)d_in[7 + o];
    const float* b1      = (const float*)d_in[8 + o];
    const float* bases   = (const float*)d_in[9 + o];
    const float* comp    = (const float*)d_in[10 + o];
    const float* w2      = (const float*)d_in[11 + o];
    const float* b2      = (const float*)d_in[12 + o];
    const float* lin_w   = (const float*)d_in[13 + o];
    const float* lin_b   = (const float*)d_in[14 + o];
    const float* fc_w    = (const float*)d_in[15 + o];
    const float* fc_b    = (const float*)d_in[16 + o];

    int N  = in_sizes[0] / F_DIM;
    int E  = in_sizes[2];
    int G  = in_sizes[4];
    int NB = in_sizes[9 + o] / (H_DIM * H_DIM);
    int R  = in_sizes[10 + o] / NB;
    float* out = (float*)d_out;
    (void)out_size;

    static cudaStream_t sA = 0, sB = 0;
    static cudaEvent_t evRoot = 0, evA = 0, evH = 0, evB2 = 0;
    if (sA == 0) {
        cudaStreamCreateWithFlags(&sA, cudaStreamNonBlocking);
        cudaStreamCreateWithFlags(&sB, cudaStreamNonBlocking);
        cudaEventCreateWithFlags(&evRoot, cudaEventDisableTiming);
        cudaEventCreateWithFlags(&evA, cudaEventDisableTiming);
        cudaEventCreateWithFlags(&evH, cudaEventDisableTiming);
        cudaEventCreateWithFlags(&evB2, cudaEventDisableTiming);
        cudaFuncSetAttribute(k_proj_mma, cudaFuncAttributeMaxDynamicSharedMemorySize,
                             128 * 68 * 8 * 2);
    }

    int chunk  = (E + NBLK_B - 1) / NBLK_B;
    int dchunk = (N + DSCAN_B - 1) / DSCAN_B;

    // fork
    cudaEventRecord(evRoot, 0);
    cudaStreamWaitEvent(sA, evRoot, 0);
    cudaStreamWaitEvent(sB, evRoot, 0);

    // stream A: all edge bucketing (independent of proj)
    k_prep<<<2048, 256, 0, sA>>>(comp, bases, R, NB, N);
    k_hist<<<NBLK_B, 256, 0, sA>>>(ei, etype, E, R, chunk);
    k_dscan1<<<DSCAN_B, 512, 0, sA>>>(N, dchunk);
    k_fscan<<<2, 1024, 0, sA>>>(R, E, N);
    k_dscan3<<<DSCAN_B, 256, 0, sA>>>(N, dchunk);
    k_scatter2<<<NBLK_B, 256, 0, sA>>>(ei, etype, enorm, E, R, chunk);
    cudaEventRecord(evA, sA);

    // stream B: graph offsets + x-half of pooling
    k_scan<<<1, 1024, 0, sB>>>(seql, G);
    k_pool_x<<<G, 128, 0, sB>>>(x, G);

    // main stream: critical path
    k_proj_mma<<<148, 512, 128 * 68 * 8 * 2>>>(x, w1_rel, w1_root, b1, N);
    cudaStreamWaitEvent(0, evA, 0);
    k_agg1b<<<(N + 7) / 8, 256>>>(N);
    cudaEventRecord(evH, 0);

    // stream B: root transform runs concurrently with rgcn3
    cudaStreamWaitEvent(sB, evH, 0);
    k_oroot_mma<<<296, 256, 0, sB>>>(w2, b2, N);
    cudaEventRecord(evB2, sB);

    // main: rgcn messages into d_o2
    k_rgcn3<<<R * 64, 256>>>(R);
    cudaStreamWaitEvent(0, evB2, 0);
    k_head2<<<G, 64>>>(lin_w, lin_b, fc_w, fc_b, out, G);
}